// round 1
// baseline (speedup 1.0000x reference)
#include <cuda_runtime.h>

// ---------------- problem constants ----------------
#define BATCH   4
#define NSEQ    8192
#define CDIM    768
#define HEADS   12
#define DHEAD   64
#define RTOT    (BATCH*NSEQ)      // 32768 rows
#define KVC     1536              // k||v feature dim
#define BHN     (BATCH*HEADS)     // 48
#define SCALE   0.125f            // D^-0.5
#define EPSLN   1e-5f

// ---------------- scratch (static device allocs; no runtime malloc) ----------------
__device__ float    g_xn[RTOT*CDIM];        // layernormed x        (96 MB)
__device__ float    g_kv[RTOT*KVC];         // k||v projections     (192 MB)
__device__ unsigned g_cmaxe[BHN*DHEAD];     // encoded column max
__device__ float    g_sumexp[BHN*DHEAD];    // softmax denominators
__device__ float    g_ctx[BHN*DHEAD*DHEAD]; // raw sum exp(k)*v
__device__ float    g_U[BATCH*CDIM*CDIM];   // U_b[hd, c3]
__device__ float    g_G[BATCH*CDIM*CDIM];   // folded matrix per batch
__device__ float    g_beff[BATCH*CDIM];     // folded bias per batch

// monotonic float<->uint encoding for atomicMax on floats
__device__ __forceinline__ unsigned fenc(float f) {
    unsigned u = __float_as_uint(f);
    return (u & 0x80000000u) ? ~u : (u | 0x80000000u);
}
__device__ __forceinline__ float fdec(unsigned u) {
    return (u & 0x80000000u) ? __uint_as_float(u & 0x7fffffffu)
                             : __uint_as_float(~u);
}

// ---------------- init accumulators ----------------
__global__ void init_k() {
    int i = blockIdx.x * blockDim.x + threadIdx.x;
    if (i < BHN*DHEAD) { g_cmaxe[i] = 0u; g_sumexp[i] = 0.f; }
    if (i < BHN*DHEAD*DHEAD) g_ctx[i] = 0.f;
}

// ---------------- LayerNorm: one block per row ----------------
__global__ __launch_bounds__(256) void ln_k(const float* __restrict__ x,
                                            const float* __restrict__ w,
                                            const float* __restrict__ b) {
    int row = blockIdx.x;
    int t = threadIdx.x;
    const float* xr = x + (long long)row * CDIM;
    float v0 = xr[t], v1 = xr[t + 256], v2 = xr[t + 512];
    float s  = v0 + v1 + v2;
    float ss = v0*v0 + v1*v1 + v2*v2;
    #pragma unroll
    for (int o = 16; o; o >>= 1) {
        s  += __shfl_xor_sync(0xffffffffu, s,  o);
        ss += __shfl_xor_sync(0xffffffffu, ss, o);
    }
    __shared__ float sh1[8], sh2[8];
    int wid = t >> 5, lid = t & 31;
    if (lid == 0) { sh1[wid] = s; sh2[wid] = ss; }
    __syncthreads();
    float ts = 0.f, tss = 0.f;
    #pragma unroll
    for (int i = 0; i < 8; i++) { ts += sh1[i]; tss += sh2[i]; }
    float mu   = ts * (1.f / CDIM);
    float var  = tss * (1.f / CDIM) - mu * mu;
    float rstd = rsqrtf(var + EPSLN);
    float* o = g_xn + (long long)row * CDIM;
    o[t]       = (v0 - mu) * rstd * w[t]       + b[t];
    o[t + 256] = (v1 - mu) * rstd * w[t + 256] + b[t + 256];
    o[t + 512] = (v2 - mu) * rstd * w[t + 512] + b[t + 512];
}

// ---------------- generic fp32 GEMM, 128x128x8 tile, 8x8 per thread ----------------
// AL==0: A[m*lda + k]   AL==1: A[k*lda + m]
// BL==0: B[n*ldb + k]   BL==1: B[k*ldb + n]
// C[m*ldc + n] = alpha * sum_k A*B + bias[n]
// All dims assumed multiples of tile sizes (true for this problem).
template<int AL, int BL>
__global__ __launch_bounds__(256)
void gemm_k(const float* __restrict__ A, const float* __restrict__ B,
            const float* __restrict__ bias, float* __restrict__ C,
            int K, int lda, int ldb, int ldc, float alpha,
            long long bsA, long long bsB, long long bsC, int bsBias) {
    __shared__ float As[8][132];
    __shared__ float Bs[8][132];
    int t = threadIdx.x;
    int tx = t & 15, ty = t >> 4;
    int n0 = blockIdx.x * 128;
    int m0 = blockIdx.y * 128;
    const float* Ab = A + (long long)blockIdx.z * bsA;
    const float* Bb = B + (long long)blockIdx.z * bsB;
    float*       Cb = C + (long long)blockIdx.z * bsC;

    float acc[8][8];
    #pragma unroll
    for (int i = 0; i < 8; i++)
        #pragma unroll
        for (int j = 0; j < 8; j++) acc[i][j] = 0.f;

    for (int k0 = 0; k0 < K; k0 += 8) {
        if (AL == 0) {
            int m = t >> 1, kq = (t & 1) * 4;
            float4 v = *(const float4*)&Ab[(long long)(m0 + m) * lda + k0 + kq];
            As[kq + 0][m] = v.x; As[kq + 1][m] = v.y;
            As[kq + 2][m] = v.z; As[kq + 3][m] = v.w;
        } else {
            int k = t >> 5, mq = (t & 31) * 4;
            *(float4*)&As[k][mq] =
                *(const float4*)&Ab[(long long)(k0 + k) * lda + m0 + mq];
        }
        if (BL == 0) {
            int n = t >> 1, kq = (t & 1) * 4;
            float4 v = *(const float4*)&Bb[(long long)(n0 + n) * ldb + k0 + kq];
            Bs[kq + 0][n] = v.x; Bs[kq + 1][n] = v.y;
            Bs[kq + 2][n] = v.z; Bs[kq + 3][n] = v.w;
        } else {
            int k = t >> 5, nq = (t & 31) * 4;
            *(float4*)&Bs[k][nq] =
                *(const float4*)&Bb[(long long)(k0 + k) * ldb + n0 + nq];
        }
        __syncthreads();
        #pragma unroll
        for (int k = 0; k < 8; k++) {
            float4 a0 = *(float4*)&As[k][ty * 8];
            float4 a1 = *(float4*)&As[k][ty * 8 + 4];
            float4 b0 = *(float4*)&Bs[k][tx * 8];
            float4 b1 = *(float4*)&Bs[k][tx * 8 + 4];
            float av[8] = {a0.x, a0.y, a0.z, a0.w, a1.x, a1.y, a1.z, a1.w};
            float bv[8] = {b0.x, b0.y, b0.z, b0.w, b1.x, b1.y, b1.z, b1.w};
            #pragma unroll
            for (int i = 0; i < 8; i++)
                #pragma unroll
                for (int j = 0; j < 8; j++)
                    acc[i][j] += av[i] * bv[j];
        }
        __syncthreads();
    }
    const float* biasb = bias ? bias + (long long)blockIdx.z * bsBias : nullptr;
    #pragma unroll
    for (int i = 0; i < 8; i++) {
        int m = m0 + ty * 8 + i;
        #pragma unroll
        for (int j = 0; j < 8; j += 4) {
            int n = n0 + tx * 8 + j;
            float4 o;
            o.x = alpha * acc[i][j + 0] + (biasb ? biasb[n + 0] : 0.f);
            o.y = alpha * acc[i][j + 1] + (biasb ? biasb[n + 1] : 0.f);
            o.z = alpha * acc[i][j + 2] + (biasb ? biasb[n + 2] : 0.f);
            o.w = alpha * acc[i][j + 3] + (biasb ? biasb[n + 3] : 0.f);
            *(float4*)&Cb[(long long)m * ldc + n] = o;
        }
    }
}

// ---------------- column max of k over sequence dim ----------------
__global__ __launch_bounds__(256) void cmax_k() {
    int bh = blockIdx.x, ch = blockIdx.y;
    int b = bh / HEADS, h = bh - b * HEADS;
    int t = threadIdx.x, d = t & 63, rg = t >> 6;
    long long base = ((long long)b * NSEQ) * KVC + h * 64 + d;
    float m = -3.4e38f;
    int n0 = ch * 512;
    #pragma unroll 4
    for (int i = 0; i < 128; i++) {
        int n = n0 + rg + i * 4;
        m = fmaxf(m, g_kv[base + (long long)n * KVC]);
    }
    __shared__ float sh[256];
    sh[t] = m;
    __syncthreads();
    if (t < 64) {
        m = fmaxf(fmaxf(sh[t], sh[t + 64]), fmaxf(sh[t + 128], sh[t + 192]));
        atomicMax(&g_cmaxe[bh * 64 + t], fenc(m));
    }
}

// ---------------- fused softmax-numerator + ctx accumulation ----------------
// g_ctx[bh][d][e] += sum_n exp(k[n,d]-max_d) * v[n,e] ; g_sumexp[bh][d] += sum_n exp(...)
__global__ __launch_bounds__(256) void ctx_k() {
    int bh = blockIdx.x, ch = blockIdx.y;
    int b = bh / HEADS, h = bh - b * HEADS;
    int t = threadIdx.x;
    __shared__ float dmax[64];
    __shared__ float sk[8][64];
    __shared__ float sv[8][64];
    if (t < 64) dmax[t] = fdec(g_cmaxe[bh * 64 + t]);
    float acc[4][4];
    #pragma unroll
    for (int i = 0; i < 4; i++)
        #pragma unroll
        for (int j = 0; j < 4; j++) acc[i][j] = 0.f;
    float seloc = 0.f;
    int d0 = (t & 15) * 4, e0 = (t >> 4) * 4;
    int dmy = t & 63;
    long long rowb = ((long long)b * NSEQ + ch * 512) * KVC + h * 64;
    __syncthreads();
    for (int tile = 0; tile < 64; tile++) {
        #pragma unroll
        for (int i = 0; i < 4; i++) {
            int f = t + i * 256;
            int r = f >> 7, c = f & 127;
            float v = g_kv[rowb + (long long)(tile * 8 + r) * KVC +
                           (c < 64 ? c : 704 + c)];
            if (c < 64) sk[r][c] = v; else sv[r][c - 64] = v;
        }
        __syncthreads();
        {
            int r = t >> 6;
            float e1 = __expf(sk[r][dmy] - dmax[dmy]);
            sk[r][dmy] = e1; seloc += e1;
            r += 4;
            float e2 = __expf(sk[r][dmy] - dmax[dmy]);
            sk[r][dmy] = e2; seloc += e2;
        }
        __syncthreads();
        #pragma unroll
        for (int r = 0; r < 8; r++) {
            float4 a  = *(float4*)&sk[r][d0];
            float4 bb = *(float4*)&sv[r][e0];
            float av[4] = {a.x, a.y, a.z, a.w};
            float bv[4] = {bb.x, bb.y, bb.z, bb.w};
            #pragma unroll
            for (int i = 0; i < 4; i++)
                #pragma unroll
                for (int j = 0; j < 4; j++) acc[i][j] += av[i] * bv[j];
        }
        __syncthreads();
    }
    __shared__ float ssum[256];
    ssum[t] = seloc;
    __syncthreads();
    if (t < 64)
        atomicAdd(&g_sumexp[bh * 64 + t],
                  ssum[t] + ssum[t + 64] + ssum[t + 128] + ssum[t + 192]);
    float* cb = &g_ctx[bh * 4096];
    #pragma unroll
    for (int i = 0; i < 4; i++)
        #pragma unroll
        for (int j = 0; j < 4; j++)
            atomicAdd(&cb[(d0 + i) * 64 + (e0 + j)], acc[i][j]);
}

// ---------------- U_b[h*64+d, c3] = sum_e (ctx[d,e]/sumexp[d]) * proj_w[c3, h*64+e] ----------------
__global__ __launch_bounds__(256) void u_k(const float* __restrict__ pw) {
    int bh = blockIdx.x;
    int c30 = blockIdx.y * 64;
    int b = bh / HEADS, h = bh - b * HEADS;
    int t = threadIdx.x;
    __shared__ float inv[64];
    __shared__ float sce[64][68];  // [e][d]
    __shared__ float spw[64][68];  // [e][c3_local]
    if (t < 64) inv[t] = 1.f / g_sumexp[bh * 64 + t];
    __syncthreads();
    #pragma unroll
    for (int i = 0; i < 16; i++) {
        int idx = t + i * 256;
        int d = idx >> 6, e = idx & 63;
        sce[e][d] = g_ctx[bh * 4096 + idx] * inv[d];
    }
    #pragma unroll
    for (int i = 0; i < 16; i++) {
        int idx = t + i * 256;
        int c3l = idx >> 6, e = idx & 63;
        spw[e][c3l] = pw[(long long)(c30 + c3l) * CDIM + h * 64 + e];
    }
    __syncthreads();
    int d0 = (t & 15) * 4, c0 = (t >> 4) * 4;
    float acc[4][4];
    #pragma unroll
    for (int i = 0; i < 4; i++)
        #pragma unroll
        for (int j = 0; j < 4; j++) acc[i][j] = 0.f;
    #pragma unroll 8
    for (int e = 0; e < 64; e++) {
        float4 a  = *(float4*)&sce[e][d0];
        float4 bb = *(float4*)&spw[e][c0];
        float av[4] = {a.x, a.y, a.z, a.w};
        float bv[4] = {bb.x, bb.y, bb.z, bb.w};
        #pragma unroll
        for (int i = 0; i < 4; i++)
            #pragma unroll
            for (int j = 0; j < 4; j++) acc[i][j] += av[i] * bv[j];
    }
    float* Ub = &g_U[(long long)b * CDIM * CDIM];
    #pragma unroll
    for (int i = 0; i < 4; i++)
        #pragma unroll
        for (int j = 0; j < 4; j++)
            Ub[(long long)(h * 64 + d0 + i) * CDIM + c30 + c0 + j] = acc[i][j];
}

// ---------------- b_eff[b][c3] = scale * sum_hd qkv_b[hd]*U_b[hd,c3] + proj_b[c3] ----------------
__global__ __launch_bounds__(256) void beff_k(const float* __restrict__ qb,
                                              const float* __restrict__ pb) {
    int b = blockIdx.x;
    int c3 = blockIdx.y * 256 + threadIdx.x;
    const float* Ub = &g_U[(long long)b * CDIM * CDIM];
    float acc = pb[c3];
    for (int hd = 0; hd < CDIM; hd++)
        acc += SCALE * qb[hd] * Ub[(long long)hd * CDIM + c3];
    g_beff[b * CDIM + c3] = acc;
}

// ---------------- launch ----------------
extern "C" void kernel_launch(void* const* d_in, const int* in_sizes, int n_in,
                              void* d_out, int out_size) {
    const float* x      = (const float*)d_in[0];
    const float* ln_w   = (const float*)d_in[1];
    const float* ln_b   = (const float*)d_in[2];
    const float* qkv_w  = (const float*)d_in[3];
    const float* qkv_b  = (const float*)d_in[4];
    const float* proj_w = (const float*)d_in[5];
    const float* proj_b = (const float*)d_in[6];
    float* out = (float*)d_out;

    static float* xn_p = nullptr;
    static float* kv_p = nullptr;
    static float* U_p = nullptr;
    static float* G_p = nullptr;
    static float* beff_p = nullptr;
    if (!xn_p) {
        cudaGetSymbolAddress((void**)&xn_p, g_xn);
        cudaGetSymbolAddress((void**)&kv_p, g_kv);
        cudaGetSymbolAddress((void**)&U_p, g_U);
        cudaGetSymbolAddress((void**)&G_p, g_G);
        cudaGetSymbolAddress((void**)&beff_p, g_beff);
    }

    // 1. reset accumulators
    init_k<<<768, 256>>>();
    // 2. LayerNorm
    ln_k<<<RTOT, 256>>>(x, ln_w, ln_b);
    // 3. kv = xn @ Wkv^T + bkv   (Wkv = qkv_w rows 768..2303)
    gemm_k<0, 0><<<dim3(KVC / 128, RTOT / 128, 1), 256>>>(
        xn_p, qkv_w + 768 * 768, qkv_b + 768, kv_p,
        CDIM, CDIM, CDIM, KVC, 1.f, 0, 0, 0, 0);
    // 4. column max of k over sequence
    cmax_k<<<dim3(BHN, 16), 256>>>();
    // 5. softmax numerator + ctx accumulation
    ctx_k<<<dim3(BHN, 16), 256>>>();
    // 6. U_b = blockdiag(ctx_norm) applied to proj_w
    u_k<<<dim3(BHN, CDIM / 64), 256>>>(proj_w);
    // 7. G_b = scale * Wq^T @ U_b   (Wq = qkv_w rows 0..767; TN layout)
    gemm_k<1, 1><<<dim3(CDIM / 128, CDIM / 128, BATCH), 256>>>(
        qkv_w, U_p, nullptr, G_p,
        CDIM, CDIM, CDIM, CDIM, SCALE,
        0, (long long)CDIM * CDIM, (long long)CDIM * CDIM, 0);
    // 8. effective bias
    beff_k<<<dim3(BATCH, CDIM / 256), 256>>>(qkv_b, proj_b);
    // 9. final = xn[b] @ G_b + b_eff[b]
    gemm_k<0, 1><<<dim3(CDIM / 128, NSEQ / 128, BATCH), 256>>>(
        xn_p, G_p, beff_p, out,
        CDIM, CDIM, CDIM, CDIM, 1.f,
        (long long)NSEQ * CDIM, (long long)CDIM * CDIM,
        (long long)NSEQ * CDIM, CDIM);
}

// round 3
// speedup vs baseline: 2.5433x; 2.5433x over previous
#include <cuda_runtime.h>

// ---------------- problem constants ----------------
#define BATCH   4
#define NSEQ    8192
#define CDIM    768
#define HEADS   12
#define DHEAD   64
#define RTOT    (BATCH*NSEQ)      // 32768 rows
#define KVC     1536              // k||v feature dim
#define BHN     (BATCH*HEADS)     // 48
#define SCALE   0.125f            // D^-0.5
#define EPSLN   1e-5f

// ---------------- scratch (static device arrays; no runtime malloc) ----------------
__device__ float g_xn[RTOT*CDIM];        // layernormed x, tf32-rounded (96 MB)
__device__ float g_kv[RTOT*KVC];         // k||v projections (192 MB)
__device__ float g_wr[KVC*CDIM];         // tf32-rounded Wkv
__device__ float g_sumexp[BHN*DHEAD];    // softmax denominators
__device__ float g_ctx[BHN*DHEAD*DHEAD]; // sum exp(k)*v
__device__ float g_U[BATCH*CDIM*CDIM];   // U_b[hd, c3]
__device__ float g_Gt[BATCH*CDIM*CDIM];  // Gt_b[c3, c] (tf32-rounded)
__device__ float g_beff[BATCH*CDIM];     // folded bias per batch

__device__ __forceinline__ float tf32r(float x) {
    unsigned u;
    asm("cvt.rna.tf32.f32 %0, %1;" : "=r"(u) : "f"(x));
    return __uint_as_float(u);
}

__device__ __forceinline__ void cp16(void* s, const void* g) {
    unsigned sa = (unsigned)__cvta_generic_to_shared(s);
    asm volatile("cp.async.cg.shared.global [%0], [%1], 16;\n" :: "r"(sa), "l"(g));
}

// ---------------- init accumulators ----------------
__global__ void init_k() {
    int i = blockIdx.x * blockDim.x + threadIdx.x;
    if (i < BHN*DHEAD) g_sumexp[i] = 0.f;
    if (i < BHN*DHEAD*DHEAD) g_ctx[i] = 0.f;
}

// ---------------- round Wkv to tf32 ----------------
__global__ void rnd_k(const float* __restrict__ w) {
    int i = blockIdx.x * blockDim.x + threadIdx.x;
    if (i < KVC*CDIM) g_wr[i] = tf32r(w[CDIM*CDIM + i]);
}

// ---------------- LayerNorm: one block per row, tf32-rounded output ----------------
__global__ __launch_bounds__(256) void ln_k(const float* __restrict__ x,
                                            const float* __restrict__ w,
                                            const float* __restrict__ b) {
    int row = blockIdx.x;
    int t = threadIdx.x;
    const float* xr = x + (long long)row * CDIM;
    float v0 = xr[t], v1 = xr[t + 256], v2 = xr[t + 512];
    float s  = v0 + v1 + v2;
    float ss = v0*v0 + v1*v1 + v2*v2;
    #pragma unroll
    for (int o = 16; o; o >>= 1) {
        s  += __shfl_xor_sync(0xffffffffu, s,  o);
        ss += __shfl_xor_sync(0xffffffffu, ss, o);
    }
    __shared__ float sh1[8], sh2[8];
    int wid = t >> 5, lid = t & 31;
    if (lid == 0) { sh1[wid] = s; sh2[wid] = ss; }
    __syncthreads();
    float ts = 0.f, tss = 0.f;
    #pragma unroll
    for (int i = 0; i < 8; i++) { ts += sh1[i]; tss += sh2[i]; }
    float mu   = ts * (1.f / CDIM);
    float var  = tss * (1.f / CDIM) - mu * mu;
    float rstd = rsqrtf(var + EPSLN);
    float* o = g_xn + (long long)row * CDIM;
    o[t]       = tf32r((v0 - mu) * rstd * w[t]       + b[t]);
    o[t + 256] = tf32r((v1 - mu) * rstd * w[t + 256] + b[t + 256]);
    o[t + 512] = tf32r((v2 - mu) * rstd * w[t + 512] + b[t + 512]);
}

// ---------------- TF32 tensor-core GEMM ----------------
// A[m][k] (row-major, lda), B[n][k] (row-major, ldb), C[m][n] = sum + bias[n]
// Tile 128x128x16, 256 threads, double-buffered cp.async.
// Dims must be multiples of 128 (M,N) and 16 (K). Inputs pre-rounded to tf32.
__global__ __launch_bounds__(256, 2)
void gemm_tf32(const float* __restrict__ A, const float* __restrict__ B,
               const float* __restrict__ bias, float* __restrict__ C,
               int K, int lda, int ldb, int ldc,
               long long bsA, long long bsB, long long bsC, int bsBias) {
    __shared__ __align__(16) float As[2][128][20];
    __shared__ __align__(16) float Bs[2][128][20];
    const int t = threadIdx.x;
    const int n0 = blockIdx.x * 128, m0 = blockIdx.y * 128;
    const float* Ab = A + (long long)blockIdx.z * bsA;
    const float* Bb = B + (long long)blockIdx.z * bsB;
    float*       Cb = C + (long long)blockIdx.z * bsC;
    const float* biasb = bias + (long long)blockIdx.z * bsBias;

    const int lane = t & 31, wid = t >> 5;
    const int wm = (wid >> 2) * 64, wn = (wid & 3) * 32;
    const int grp = lane >> 2, thr = lane & 3;

    // loader indices: 256 threads x 2 iters cover 128 rows x 4 float4 per matrix
    const int ldr_row = t >> 2, ldr_c4 = (t & 3) << 2;
    const int ldr_row2 = (t + 256) >> 2, ldr_c42 = ((t + 256) & 3) << 2;

    float c[4][4][4];
    #pragma unroll
    for (int i = 0; i < 4; i++)
        #pragma unroll
        for (int j = 0; j < 4; j++)
            #pragma unroll
            for (int q = 0; q < 4; q++) c[i][j][q] = 0.f;

    // prologue stage 0
    cp16(&As[0][ldr_row][ldr_c4],  Ab + (long long)(m0 + ldr_row)  * lda + ldr_c4);
    cp16(&Bs[0][ldr_row][ldr_c4],  Bb + (long long)(n0 + ldr_row)  * ldb + ldr_c4);
    cp16(&As[0][ldr_row2][ldr_c42], Ab + (long long)(m0 + ldr_row2) * lda + ldr_c42);
    cp16(&Bs[0][ldr_row2][ldr_c42], Bb + (long long)(n0 + ldr_row2) * ldb + ldr_c42);
    asm volatile("cp.async.commit_group;\n");

    const int T = K >> 4;
    for (int tt = 0; tt < T; tt++) {
        if (tt + 1 < T) {
            const int s1 = (tt + 1) & 1;
            const int k1 = (tt + 1) << 4;
            cp16(&As[s1][ldr_row][k1 % 16 + ldr_c4],  // k offset within stage is ldr_c4 only
                 Ab + (long long)(m0 + ldr_row) * lda + k1 + ldr_c4);
            cp16(&Bs[s1][ldr_row][ldr_c4],
                 Bb + (long long)(n0 + ldr_row) * ldb + k1 + ldr_c4);
            cp16(&As[s1][ldr_row2][ldr_c42],
                 Ab + (long long)(m0 + ldr_row2) * lda + k1 + ldr_c42);
            cp16(&Bs[s1][ldr_row2][ldr_c42],
                 Bb + (long long)(n0 + ldr_row2) * ldb + k1 + ldr_c42);
            asm volatile("cp.async.commit_group;\n");
            asm volatile("cp.async.wait_group 1;\n" ::: "memory");
        } else {
            asm volatile("cp.async.wait_group 0;\n" ::: "memory");
        }
        __syncthreads();
        const int s = tt & 1;
        #pragma unroll
        for (int kk = 0; kk < 16; kk += 8) {
            unsigned a[4][4], b[4][2];
            #pragma unroll
            for (int mi = 0; mi < 4; mi++) {
                int r = wm + mi * 16 + grp;
                a[mi][0] = __float_as_uint(As[s][r    ][kk + thr]);
                a[mi][1] = __float_as_uint(As[s][r + 8][kk + thr]);
                a[mi][2] = __float_as_uint(As[s][r    ][kk + thr + 4]);
                a[mi][3] = __float_as_uint(As[s][r + 8][kk + thr + 4]);
            }
            #pragma unroll
            for (int nj = 0; nj < 4; nj++) {
                int cc = wn + nj * 8 + grp;
                b[nj][0] = __float_as_uint(Bs[s][cc][kk + thr]);
                b[nj][1] = __float_as_uint(Bs[s][cc][kk + thr + 4]);
            }
            #pragma unroll
            for (int mi = 0; mi < 4; mi++)
                #pragma unroll
                for (int nj = 0; nj < 4; nj++)
                    asm volatile(
                        "mma.sync.aligned.m16n8k8.row.col.f32.tf32.tf32.f32 "
                        "{%0,%1,%2,%3}, {%4,%5,%6,%7}, {%8,%9}, {%0,%1,%2,%3};\n"
                        : "+f"(c[mi][nj][0]), "+f"(c[mi][nj][1]),
                          "+f"(c[mi][nj][2]), "+f"(c[mi][nj][3])
                        : "r"(a[mi][0]), "r"(a[mi][1]), "r"(a[mi][2]), "r"(a[mi][3]),
                          "r"(b[nj][0]), "r"(b[nj][1]));
        }
        __syncthreads();
    }

    #pragma unroll
    for (int mi = 0; mi < 4; mi++) {
        #pragma unroll
        for (int nj = 0; nj < 4; nj++) {
            int m = m0 + wm + mi * 16 + grp;
            int n = n0 + wn + nj * 8 + 2 * thr;
            float bi0 = biasb[n], bi1 = biasb[n + 1];
            float2 v0 = make_float2(c[mi][nj][0] + bi0, c[mi][nj][1] + bi1);
            float2 v1 = make_float2(c[mi][nj][2] + bi0, c[mi][nj][3] + bi1);
            *(float2*)&Cb[(long long)m * ldc + n] = v0;
            *(float2*)&Cb[(long long)(m + 8) * ldc + n] = v1;
        }
    }
}

// ---------------- fp32 SIMT GEMM (small compose step only) ----------------
// A[k*lda + m], B[k*ldb + n], C[m*ldc+n] = tf32r(alpha * sum)
__global__ __launch_bounds__(256)
void gemm_tn(const float* __restrict__ A, const float* __restrict__ B,
             float* __restrict__ C, int K, int lda, int ldb, int ldc,
             float alpha, long long bsA, long long bsB, long long bsC) {
    __shared__ float As[8][132];
    __shared__ float Bs[8][132];
    int t = threadIdx.x;
    int tx = t & 15, ty = t >> 4;
    int n0 = blockIdx.x * 128;
    int m0 = blockIdx.y * 128;
    const float* Ab = A + (long long)blockIdx.z * bsA;
    const float* Bb = B + (long long)blockIdx.z * bsB;
    float*       Cb = C + (long long)blockIdx.z * bsC;

    float acc[8][8];
    #pragma unroll
    for (int i = 0; i < 8; i++)
        #pragma unroll
        for (int j = 0; j < 8; j++) acc[i][j] = 0.f;

    for (int k0 = 0; k0 < K; k0 += 8) {
        {
            int k = t >> 5, mq = (t & 31) * 4;
            *(float4*)&As[k][mq] =
                *(const float4*)&Ab[(long long)(k0 + k) * lda + m0 + mq];
            *(float4*)&Bs[k][mq] =
                *(const float4*)&Bb[(long long)(k0 + k) * ldb + n0 + mq];
        }
        __syncthreads();
        #pragma unroll
        for (int k = 0; k < 8; k++) {
            float4 a0 = *(float4*)&As[k][ty * 8];
            float4 a1 = *(float4*)&As[k][ty * 8 + 4];
            float4 b0 = *(float4*)&Bs[k][tx * 8];
            float4 b1 = *(float4*)&Bs[k][tx * 8 + 4];
            float av[8] = {a0.x, a0.y, a0.z, a0.w, a1.x, a1.y, a1.z, a1.w};
            float bv[8] = {b0.x, b0.y, b0.z, b0.w, b1.x, b1.y, b1.z, b1.w};
            #pragma unroll
            for (int i = 0; i < 8; i++)
                #pragma unroll
                for (int j = 0; j < 8; j++)
                    acc[i][j] += av[i] * bv[j];
        }
        __syncthreads();
    }
    #pragma unroll
    for (int i = 0; i < 8; i++) {
        int m = m0 + ty * 8 + i;
        #pragma unroll
        for (int j = 0; j < 8; j += 4) {
            int n = n0 + tx * 8 + j;
            float4 o;
            o.x = tf32r(alpha * acc[i][j + 0]);
            o.y = tf32r(alpha * acc[i][j + 1]);
            o.z = tf32r(alpha * acc[i][j + 2]);
            o.w = tf32r(alpha * acc[i][j + 3]);
            *(float4*)&Cb[(long long)m * ldc + n] = o;
        }
    }
}

// ---------------- fused softmax-numerator + ctx accumulation (no max shift) ----------------
__global__ __launch_bounds__(256) void ctx_k() {
    int bh = blockIdx.x, ch = blockIdx.y;
    int b = bh / HEADS, h = bh - b * HEADS;
    int t = threadIdx.x;
    __shared__ float sk[8][64];
    __shared__ float sv[8][64];
    float acc[4][4];
    #pragma unroll
    for (int i = 0; i < 4; i++)
        #pragma unroll
        for (int j = 0; j < 4; j++) acc[i][j] = 0.f;
    float seloc = 0.f;
    int d0 = (t & 15) * 4, e0 = (t >> 4) * 4;
    int dmy = t & 63;
    long long rowb = ((long long)b * NSEQ + ch * 512) * KVC + h * 64;
    for (int tile = 0; tile < 64; tile++) {
        #pragma unroll
        for (int i = 0; i < 4; i++) {
            int f = t + i * 256;
            int r = f >> 7, c = f & 127;
            float v = g_kv[rowb + (long long)(tile * 8 + r) * KVC +
                           (c < 64 ? c : 704 + c)];
            if (c < 64) sk[r][c] = v; else sv[r][c - 64] = v;
        }
        __syncthreads();
        {
            int r = t >> 6;
            float e1 = __expf(sk[r][dmy]);
            sk[r][dmy] = e1; seloc += e1;
            r += 4;
            float e2 = __expf(sk[r][dmy]);
            sk[r][dmy] = e2; seloc += e2;
        }
        __syncthreads();
        #pragma unroll
        for (int r = 0; r < 8; r++) {
            float4 a  = *(float4*)&sk[r][d0];
            float4 bb = *(float4*)&sv[r][e0];
            float av[4] = {a.x, a.y, a.z, a.w};
            float bv[4] = {bb.x, bb.y, bb.z, bb.w};
            #pragma unroll
            for (int i = 0; i < 4; i++)
                #pragma unroll
                for (int j = 0; j < 4; j++) acc[i][j] += av[i] * bv[j];
        }
        __syncthreads();
    }
    __shared__ float ssum[256];
    ssum[t] = seloc;
    __syncthreads();
    if (t < 64)
        atomicAdd(&g_sumexp[bh * 64 + t],
                  ssum[t] + ssum[t + 64] + ssum[t + 128] + ssum[t + 192]);
    float* cb = &g_ctx[bh * 4096];
    #pragma unroll
    for (int i = 0; i < 4; i++)
        #pragma unroll
        for (int j = 0; j < 4; j++)
            atomicAdd(&cb[(d0 + i) * 64 + (e0 + j)], acc[i][j]);
}

// ---------------- U_b[h*64+d, c3] = sum_e (ctx[d,e]/sumexp[d]) * proj_w[c3, h*64+e] ----------------
__global__ __launch_bounds__(256) void u_k(const float* __restrict__ pw) {
    int bh = blockIdx.x;
    int c30 = blockIdx.y * 64;
    int b = bh / HEADS, h = bh - b * HEADS;
    int t = threadIdx.x;
    __shared__ float inv[64];
    __shared__ float sce[64][68];  // [e][d]
    __shared__ float spw[64][68];  // [e][c3_local]
    if (t < 64) inv[t] = 1.f / g_sumexp[bh * 64 + t];
    __syncthreads();
    #pragma unroll
    for (int i = 0; i < 16; i++) {
        int idx = t + i * 256;
        int d = idx >> 6, e = idx & 63;
        sce[e][d] = g_ctx[bh * 4096 + idx] * inv[d];
    }
    #pragma unroll
    for (int i = 0; i < 16; i++) {
        int idx = t + i * 256;
        int c3l = idx >> 6, e = idx & 63;
        spw[e][c3l] = pw[(long long)(c30 + c3l) * CDIM + h * 64 + e];
    }
    __syncthreads();
    int d0 = (t & 15) * 4, c0 = (t >> 4) * 4;
    float acc[4][4];
    #pragma unroll
    for (int i = 0; i < 4; i++)
        #pragma unroll
        for (int j = 0; j < 4; j++) acc[i][j] = 0.f;
    #pragma unroll 8
    for (int e = 0; e < 64; e++) {
        float4 a  = *(float4*)&sce[e][d0];
        float4 bb = *(float4*)&spw[e][c0];
        float av[4] = {a.x, a.y, a.z, a.w};
        float bv[4] = {bb.x, bb.y, bb.z, bb.w};
        #pragma unroll
        for (int i = 0; i < 4; i++)
            #pragma unroll
            for (int j = 0; j < 4; j++) acc[i][j] += av[i] * bv[j];
    }
    float* Ub = &g_U[(long long)b * CDIM * CDIM];
    #pragma unroll
    for (int i = 0; i < 4; i++)
        #pragma unroll
        for (int j = 0; j < 4; j++)
            Ub[(long long)(h * 64 + d0 + i) * CDIM + c30 + c0 + j] = acc[i][j];
}

// ---------------- b_eff[b][c3] = scale * sum_hd qkv_b[hd]*U_b[hd,c3] + proj_b[c3] ----------------
__global__ __launch_bounds__(256) void beff_k(const float* __restrict__ qb,
                                              const float* __restrict__ pb) {
    int b = blockIdx.x;
    int c3 = blockIdx.y * 256 + threadIdx.x;
    const float* Ub = &g_U[(long long)b * CDIM * CDIM];
    float acc = pb[c3];
    #pragma unroll 8
    for (int hd = 0; hd < CDIM; hd++)
        acc += SCALE * qb[hd] * Ub[(long long)hd * CDIM + c3];
    g_beff[b * CDIM + c3] = acc;
}

// ---------------- launch ----------------
extern "C" void kernel_launch(void* const* d_in, const int* in_sizes, int n_in,
                              void* d_out, int out_size) {
    const float* x      = (const float*)d_in[0];
    const float* ln_w   = (const float*)d_in[1];
    const float* ln_b   = (const float*)d_in[2];
    const float* qkv_w  = (const float*)d_in[3];
    const float* qkv_b  = (const float*)d_in[4];
    const float* proj_w = (const float*)d_in[5];
    const float* proj_b = (const float*)d_in[6];
    float* out = (float*)d_out;

    static float* xn_p = nullptr;
    static float* kv_p = nullptr;
    static float* wr_p = nullptr;
    static float* U_p = nullptr;
    static float* Gt_p = nullptr;
    static float* beff_p = nullptr;
    if (!xn_p) {
        cudaGetSymbolAddress((void**)&xn_p, g_xn);
        cudaGetSymbolAddress((void**)&kv_p, g_kv);
        cudaGetSymbolAddress((void**)&wr_p, g_wr);
        cudaGetSymbolAddress((void**)&U_p, g_U);
        cudaGetSymbolAddress((void**)&Gt_p, g_Gt);
        cudaGetSymbolAddress((void**)&beff_p, g_beff);
    }

    // 1. reset accumulators
    init_k<<<768, 256>>>();
    // 2. round Wkv to tf32
    rnd_k<<<(KVC * CDIM + 255) / 256, 256>>>(qkv_w);
    // 3. LayerNorm (tf32-rounded output)
    ln_k<<<RTOT, 256>>>(x, ln_w, ln_b);
    // 4. kv = xn @ Wkv^T + bkv   (tensor cores, tf32)
    gemm_tf32<<<dim3(KVC / 128, RTOT / 128, 1), 256>>>(
        xn_p, wr_p, qkv_b + CDIM, kv_p,
        CDIM, CDIM, CDIM, KVC, 0, 0, 0, 0);
    // 5. softmax numerator + ctx accumulation (no max shift needed)
    ctx_k<<<dim3(BHN, 16), 256>>>();
    // 6. U_b = blockdiag(ctx_norm) applied to proj_w
    u_k<<<dim3(BHN, CDIM / 64), 256>>>(proj_w);
    // 7. effective bias
    beff_k<<<dim3(BATCH, CDIM / 256), 256>>>(qkv_b, proj_b);
    // 8. Gt_b[c3, c] = scale * sum_hd U_b[hd,c3] * Wq[hd,c]  (fp32 SIMT, round to tf32)
    gemm_tn<<<dim3(CDIM / 128, CDIM / 128, BATCH), 256>>>(
        U_p, qkv_w, Gt_p, CDIM, CDIM, CDIM, CDIM, SCALE,
        (long long)CDIM * CDIM, 0, (long long)CDIM * CDIM);
    // 9. final = xn[b] @ Gt_b^T + b_eff[b]   (tensor cores, tf32)
    gemm_tf32<<<dim3(CDIM / 128, NSEQ / 128, BATCH), 256>>>(
        xn_p, Gt_p, beff_p, out,
        CDIM, CDIM, CDIM, CDIM,
        (long long)NSEQ * CDIM, (long long)CDIM * CDIM,
        (long long)NSEQ * CDIM, CDIM);
}

// round 4
// speedup vs baseline: 2.9186x; 1.1476x over previous
#include <cuda_runtime.h>

// ---------------- problem constants ----------------
#define BATCH   4
#define NSEQ    8192
#define CDIM    768
#define HEADS   12
#define DHEAD   64
#define RTOT    (BATCH*NSEQ)      // 32768 rows
#define KVC     1536              // k||v feature dim
#define BHN     (BATCH*HEADS)     // 48
#define SCALE   0.125f            // D^-0.5
#define EPSLN   1e-5f

// ---------------- scratch (static device arrays; no runtime malloc) ----------------
__device__ float g_xn[RTOT*CDIM];        // layernormed x, tf32-rounded (96 MB)
__device__ float g_kv[RTOT*KVC];         // k||v projections (192 MB)
__device__ float g_wr[KVC*CDIM];         // tf32-rounded Wkv
__device__ float g_sumexp[BHN*DHEAD];    // softmax denominators
__device__ float g_ctx[BHN*DHEAD*DHEAD]; // sum exp(k)*v
__device__ float g_U[BATCH*CDIM*CDIM];   // U_b[hd, c3]
__device__ float g_Gt[BATCH*CDIM*CDIM];  // Gt_b[c3, c] (tf32-rounded)
__device__ float g_beff[BATCH*CDIM];     // folded bias per batch

__device__ __forceinline__ float tf32r(float x) {
    unsigned u;
    asm("cvt.rna.tf32.f32 %0, %1;" : "=r"(u) : "f"(x));
    return __uint_as_float(u);
}

__device__ __forceinline__ void cp16(void* s, const void* g) {
    unsigned sa = (unsigned)__cvta_generic_to_shared(s);
    asm volatile("cp.async.cg.shared.global [%0], [%1], 16;\n" :: "r"(sa), "l"(g));
}

// ---------------- init accumulators ----------------
__global__ void init_k() {
    int i = blockIdx.x * blockDim.x + threadIdx.x;
    if (i < BHN*DHEAD) g_sumexp[i] = 0.f;
    if (i < BHN*DHEAD*DHEAD) g_ctx[i] = 0.f;
}

// ---------------- round Wkv to tf32 ----------------
__global__ void rnd_k(const float* __restrict__ w) {
    int i = blockIdx.x * blockDim.x + threadIdx.x;
    if (i < KVC*CDIM) g_wr[i] = tf32r(w[CDIM*CDIM + i]);
}

// ---------------- LayerNorm: one block per row, tf32-rounded output ----------------
__global__ __launch_bounds__(256) void ln_k(const float* __restrict__ x,
                                            const float* __restrict__ w,
                                            const float* __restrict__ b) {
    int row = blockIdx.x;
    int t = threadIdx.x;
    const float* xr = x + (long long)row * CDIM;
    float v0 = xr[t], v1 = xr[t + 256], v2 = xr[t + 512];
    float s  = v0 + v1 + v2;
    float ss = v0*v0 + v1*v1 + v2*v2;
    #pragma unroll
    for (int o = 16; o; o >>= 1) {
        s  += __shfl_xor_sync(0xffffffffu, s,  o);
        ss += __shfl_xor_sync(0xffffffffu, ss, o);
    }
    __shared__ float sh1[8], sh2[8];
    int wid = t >> 5, lid = t & 31;
    if (lid == 0) { sh1[wid] = s; sh2[wid] = ss; }
    __syncthreads();
    float ts = 0.f, tss = 0.f;
    #pragma unroll
    for (int i = 0; i < 8; i++) { ts += sh1[i]; tss += sh2[i]; }
    float mu   = ts * (1.f / CDIM);
    float var  = tss * (1.f / CDIM) - mu * mu;
    float rstd = rsqrtf(var + EPSLN);
    float* o = g_xn + (long long)row * CDIM;
    o[t]       = tf32r((v0 - mu) * rstd * w[t]       + b[t]);
    o[t + 256] = tf32r((v1 - mu) * rstd * w[t + 256] + b[t + 256]);
    o[t + 512] = tf32r((v2 - mu) * rstd * w[t + 512] + b[t + 512]);
}

// ---------------- TF32 tensor-core GEMM, 4-stage pipeline, swizzled smem ----------------
// A[m][k] (row-major, lda), B[n][k] (row-major, ldb), C[m][n] = sum + bias[n]
// Tile 128x128x16, 256 threads, 4-stage cp.async, XOR-swizzled [128][16] stages.
// Fragment loads use float2 with a virtual-k permutation (thread thr covers smem
// cols {2thr, 2thr+1} for BOTH A and B, which is a valid reordering of the k8 sum).
// Dims must be multiples of 128 (M,N) and 16 (K). Inputs pre-rounded to tf32.
#define GSTAGES 4
#define GSMEM_FLOATS (GSTAGES * 128 * 16)       // per matrix
#define GSMEM_BYTES  (2 * GSMEM_FLOATS * 4)     // 65536

__global__ __launch_bounds__(256, 2)
void gemm_tf32(const float* __restrict__ A, const float* __restrict__ B,
               const float* __restrict__ bias, float* __restrict__ C,
               int K, int lda, int ldb, int ldc,
               long long bsA, long long bsB, long long bsC, int bsBias) {
    extern __shared__ float smem[];
    float* As = smem;                 // [GSTAGES][128][16], swizzled
    float* Bs = smem + GSMEM_FLOATS;  // [GSTAGES][128][16], swizzled

    const int t = threadIdx.x;
    const int n0 = blockIdx.x * 128, m0 = blockIdx.y * 128;
    const float* Ab = A + (long long)blockIdx.z * bsA;
    const float* Bb = B + (long long)blockIdx.z * bsB;
    float*       Cb = C + (long long)blockIdx.z * bsC;
    const float* biasb = bias + (long long)blockIdx.z * bsBias;

    const int lane = t & 31, wid = t >> 5;
    const int wm = (wid >> 2) * 64, wn = (wid & 3) * 32;
    const int grp = lane >> 2, thr = lane & 3;

    // loader: 256 threads x 2 iters cover 128 rows x 4 16B-chunks per matrix
    const int lr1 = t >> 2,        lc1 = (t & 3) << 2;
    const int lr2 = lr1 + 64;      // second batch of rows
    const int sc1 = lc1 ^ ((lr1 & 3) << 2);   // swizzled col
    const int sc2 = lc1 ^ ((lr2 & 3) << 2);

    float c[4][4][4];
    #pragma unroll
    for (int i = 0; i < 4; i++)
        #pragma unroll
        for (int j = 0; j < 4; j++)
            #pragma unroll
            for (int q = 0; q < 4; q++) c[i][j][q] = 0.f;

    // issue one stage's loads
    #define G_ISSUE(slot, k0)                                                   \
        do {                                                                    \
            float* as_ = As + ((slot) * 128 << 4);                              \
            float* bs_ = Bs + ((slot) * 128 << 4);                              \
            cp16(&as_[(lr1 << 4) + sc1], Ab + (long long)(m0 + lr1) * lda + (k0) + lc1); \
            cp16(&bs_[(lr1 << 4) + sc1], Bb + (long long)(n0 + lr1) * ldb + (k0) + lc1); \
            cp16(&as_[(lr2 << 4) + sc2], Ab + (long long)(m0 + lr2) * lda + (k0) + lc1); \
            cp16(&bs_[(lr2 << 4) + sc2], Bb + (long long)(n0 + lr2) * ldb + (k0) + lc1); \
            asm volatile("cp.async.commit_group;\n");                           \
        } while (0)

    const int T = K >> 4;
    // prologue: stages 0..2
    G_ISSUE(0, 0);
    G_ISSUE(1, 16);
    G_ISSUE(2, 32);

    for (int tt = 0; tt < T; tt++) {
        asm volatile("cp.async.wait_group 2;\n" ::: "memory");
        __syncthreads();
        if (tt + 3 < T) {
            G_ISSUE((tt + 3) & (GSTAGES - 1), (tt + 3) << 4);
        } else {
            asm volatile("cp.async.commit_group;\n");  // keep group count uniform
        }
        const int s = tt & (GSTAGES - 1);
        const float* as_ = As + (s * 128 << 4);
        const float* bs_ = Bs + (s * 128 << 4);
        #pragma unroll
        for (int kk = 0; kk < 16; kk += 8) {
            // virtual-k float2 fragment loads
            float2 af[4][2];
            float2 bf[4];
            #pragma unroll
            for (int mi = 0; mi < 4; mi++) {
                int r = wm + mi * 16 + grp;
                int col = (kk + 2 * thr) ^ ((r & 3) << 2);
                af[mi][0] = *(const float2*)&as_[(r << 4) + col];
                af[mi][1] = *(const float2*)&as_[((r + 8) << 4) + col];
            }
            #pragma unroll
            for (int nj = 0; nj < 4; nj++) {
                int cc = wn + nj * 8 + grp;
                int col = (kk + 2 * thr) ^ ((cc & 3) << 2);
                bf[nj] = *(const float2*)&bs_[(cc << 4) + col];
            }
            #pragma unroll
            for (int mi = 0; mi < 4; mi++)
                #pragma unroll
                for (int nj = 0; nj < 4; nj++)
                    asm volatile(
                        "mma.sync.aligned.m16n8k8.row.col.f32.tf32.tf32.f32 "
                        "{%0,%1,%2,%3}, {%4,%5,%6,%7}, {%8,%9}, {%0,%1,%2,%3};\n"
                        : "+f"(c[mi][nj][0]), "+f"(c[mi][nj][1]),
                          "+f"(c[mi][nj][2]), "+f"(c[mi][nj][3])
                        : "r"(__float_as_uint(af[mi][0].x)),
                          "r"(__float_as_uint(af[mi][1].x)),
                          "r"(__float_as_uint(af[mi][0].y)),
                          "r"(__float_as_uint(af[mi][1].y)),
                          "r"(__float_as_uint(bf[nj].x)),
                          "r"(__float_as_uint(bf[nj].y)));
        }
        __syncthreads();
    }

    #pragma unroll
    for (int mi = 0; mi < 4; mi++) {
        #pragma unroll
        for (int nj = 0; nj < 4; nj++) {
            int m = m0 + wm + mi * 16 + grp;
            int n = n0 + wn + nj * 8 + 2 * thr;
            float bi0 = biasb[n], bi1 = biasb[n + 1];
            float2 v0 = make_float2(c[mi][nj][0] + bi0, c[mi][nj][1] + bi1);
            float2 v1 = make_float2(c[mi][nj][2] + bi0, c[mi][nj][3] + bi1);
            *(float2*)&Cb[(long long)m * ldc + n] = v0;
            *(float2*)&Cb[(long long)(m + 8) * ldc + n] = v1;
        }
    }
}

// ---------------- fp32 SIMT GEMM (small compose step only) ----------------
// A[k*lda + m], B[k*ldb + n], C[m*ldc+n] = tf32r(alpha * sum)
__global__ __launch_bounds__(256)
void gemm_tn(const float* __restrict__ A, const float* __restrict__ B,
             float* __restrict__ C, int K, int lda, int ldb, int ldc,
             float alpha, long long bsA, long long bsB, long long bsC) {
    __shared__ float As[8][132];
    __shared__ float Bs[8][132];
    int t = threadIdx.x;
    int tx = t & 15, ty = t >> 4;
    int n0 = blockIdx.x * 128;
    int m0 = blockIdx.y * 128;
    const float* Ab = A + (long long)blockIdx.z * bsA;
    const float* Bb = B + (long long)blockIdx.z * bsB;
    float*       Cb = C + (long long)blockIdx.z * bsC;

    float acc[8][8];
    #pragma unroll
    for (int i = 0; i < 8; i++)
        #pragma unroll
        for (int j = 0; j < 8; j++) acc[i][j] = 0.f;

    for (int k0 = 0; k0 < K; k0 += 8) {
        {
            int k = t >> 5, mq = (t & 31) * 4;
            *(float4*)&As[k][mq] =
                *(const float4*)&Ab[(long long)(k0 + k) * lda + m0 + mq];
            *(float4*)&Bs[k][mq] =
                *(const float4*)&Bb[(long long)(k0 + k) * ldb + n0 + mq];
        }
        __syncthreads();
        #pragma unroll
        for (int k = 0; k < 8; k++) {
            float4 a0 = *(float4*)&As[k][ty * 8];
            float4 a1 = *(float4*)&As[k][ty * 8 + 4];
            float4 b0 = *(float4*)&Bs[k][tx * 8];
            float4 b1 = *(float4*)&Bs[k][tx * 8 + 4];
            float av[8] = {a0.x, a0.y, a0.z, a0.w, a1.x, a1.y, a1.z, a1.w};
            float bv[8] = {b0.x, b0.y, b0.z, b0.w, b1.x, b1.y, b1.z, b1.w};
            #pragma unroll
            for (int i = 0; i < 8; i++)
                #pragma unroll
                for (int j = 0; j < 8; j++)
                    acc[i][j] += av[i] * bv[j];
        }
        __syncthreads();
    }
    #pragma unroll
    for (int i = 0; i < 8; i++) {
        int m = m0 + ty * 8 + i;
        #pragma unroll
        for (int j = 0; j < 8; j += 4) {
            int n = n0 + tx * 8 + j;
            float4 o;
            o.x = tf32r(alpha * acc[i][j + 0]);
            o.y = tf32r(alpha * acc[i][j + 1]);
            o.z = tf32r(alpha * acc[i][j + 2]);
            o.w = tf32r(alpha * acc[i][j + 3]);
            *(float4*)&Cb[(long long)m * ldc + n] = o;
        }
    }
}

// ---------------- fused softmax-numerator + ctx accumulation (no max shift) ----------------
__global__ __launch_bounds__(256) void ctx_k() {
    int bh = blockIdx.x, ch = blockIdx.y;
    int b = bh / HEADS, h = bh - b * HEADS;
    int t = threadIdx.x;
    __shared__ float sk[8][64];
    __shared__ float sv[8][64];
    float acc[4][4];
    #pragma unroll
    for (int i = 0; i < 4; i++)
        #pragma unroll
        for (int j = 0; j < 4; j++) acc[i][j] = 0.f;
    float seloc = 0.f;
    int d0 = (t & 15) * 4, e0 = (t >> 4) * 4;
    int dmy = t & 63;
    long long rowb = ((long long)b * NSEQ + ch * 512) * KVC + h * 64;
    for (int tile = 0; tile < 64; tile++) {
        #pragma unroll
        for (int i = 0; i < 4; i++) {
            int f = t + i * 256;
            int r = f >> 7, c = f & 127;
            float v = g_kv[rowb + (long long)(tile * 8 + r) * KVC +
                           (c < 64 ? c : 704 + c)];
            if (c < 64) sk[r][c] = v; else sv[r][c - 64] = v;
        }
        __syncthreads();
        {
            int r = t >> 6;
            float e1 = __expf(sk[r][dmy]);
            sk[r][dmy] = e1; seloc += e1;
            r += 4;
            float e2 = __expf(sk[r][dmy]);
            sk[r][dmy] = e2; seloc += e2;
        }
        __syncthreads();
        #pragma unroll
        for (int r = 0; r < 8; r++) {
            float4 a  = *(float4*)&sk[r][d0];
            float4 bb = *(float4*)&sv[r][e0];
            float av[4] = {a.x, a.y, a.z, a.w};
            float bv[4] = {bb.x, bb.y, bb.z, bb.w};
            #pragma unroll
            for (int i = 0; i < 4; i++)
                #pragma unroll
                for (int j = 0; j < 4; j++) acc[i][j] += av[i] * bv[j];
        }
        __syncthreads();
    }
    __shared__ float ssum[256];
    ssum[t] = seloc;
    __syncthreads();
    if (t < 64)
        atomicAdd(&g_sumexp[bh * 64 + t],
                  ssum[t] + ssum[t + 64] + ssum[t + 128] + ssum[t + 192]);
    float* cb = &g_ctx[bh * 4096];
    #pragma unroll
    for (int i = 0; i < 4; i++)
        #pragma unroll
        for (int j = 0; j < 4; j++)
            atomicAdd(&cb[(d0 + i) * 64 + (e0 + j)], acc[i][j]);
}

// ---------------- U_b[h*64+d, c3] = sum_e (ctx[d,e]/sumexp[d]) * proj_w[c3, h*64+e] ----------------
__global__ __launch_bounds__(256) void u_k(const float* __restrict__ pw) {
    int bh = blockIdx.x;
    int c30 = blockIdx.y * 64;
    int b = bh / HEADS, h = bh - b * HEADS;
    int t = threadIdx.x;
    __shared__ float inv[64];
    __shared__ float sce[64][68];  // [e][d]
    __shared__ float spw[64][68];  // [e][c3_local]
    if (t < 64) inv[t] = 1.f / g_sumexp[bh * 64 + t];
    __syncthreads();
    #pragma unroll
    for (int i = 0; i < 16; i++) {
        int idx = t + i * 256;
        int d = idx >> 6, e = idx & 63;
        sce[e][d] = g_ctx[bh * 4096 + idx] * inv[d];
    }
    #pragma unroll
    for (int i = 0; i < 16; i++) {
        int idx = t + i * 256;
        int c3l = idx >> 6, e = idx & 63;
        spw[e][c3l] = pw[(long long)(c30 + c3l) * CDIM + h * 64 + e];
    }
    __syncthreads();
    int d0 = (t & 15) * 4, c0 = (t >> 4) * 4;
    float acc[4][4];
    #pragma unroll
    for (int i = 0; i < 4; i++)
        #pragma unroll
        for (int j = 0; j < 4; j++) acc[i][j] = 0.f;
    #pragma unroll 8
    for (int e = 0; e < 64; e++) {
        float4 a  = *(float4*)&sce[e][d0];
        float4 bb = *(float4*)&spw[e][c0];
        float av[4] = {a.x, a.y, a.z, a.w};
        float bv[4] = {bb.x, bb.y, bb.z, bb.w};
        #pragma unroll
        for (int i = 0; i < 4; i++)
            #pragma unroll
            for (int j = 0; j < 4; j++) acc[i][j] += av[i] * bv[j];
    }
    float* Ub = &g_U[(long long)b * CDIM * CDIM];
    #pragma unroll
    for (int i = 0; i < 4; i++)
        #pragma unroll
        for (int j = 0; j < 4; j++)
            Ub[(long long)(h * 64 + d0 + i) * CDIM + c30 + c0 + j] = acc[i][j];
}

// ---------------- b_eff[b][c3] = scale * sum_hd qkv_b[hd]*U_b[hd,c3] + proj_b[c3] ----------------
__global__ __launch_bounds__(256) void beff_k(const float* __restrict__ qb,
                                              const float* __restrict__ pb) {
    int b = blockIdx.x;
    int c3 = blockIdx.y * 256 + threadIdx.x;
    const float* Ub = &g_U[(long long)b * CDIM * CDIM];
    float acc = pb[c3];
    #pragma unroll 8
    for (int hd = 0; hd < CDIM; hd++)
        acc += SCALE * qb[hd] * Ub[(long long)hd * CDIM + c3];
    g_beff[b * CDIM + c3] = acc;
}

// ---------------- launch ----------------
extern "C" void kernel_launch(void* const* d_in, const int* in_sizes, int n_in,
                              void* d_out, int out_size) {
    const float* x      = (const float*)d_in[0];
    const float* ln_w   = (const float*)d_in[1];
    const float* ln_b   = (const float*)d_in[2];
    const float* qkv_w  = (const float*)d_in[3];
    const float* qkv_b  = (const float*)d_in[4];
    const float* proj_w = (const float*)d_in[5];
    const float* proj_b = (const float*)d_in[6];
    float* out = (float*)d_out;

    static float* xn_p = nullptr;
    static float* kv_p = nullptr;
    static float* wr_p = nullptr;
    static float* U_p = nullptr;
    static float* Gt_p = nullptr;
    static float* beff_p = nullptr;
    if (!xn_p) {
        cudaGetSymbolAddress((void**)&xn_p, g_xn);
        cudaGetSymbolAddress((void**)&kv_p, g_kv);
        cudaGetSymbolAddress((void**)&wr_p, g_wr);
        cudaGetSymbolAddress((void**)&U_p, g_U);
        cudaGetSymbolAddress((void**)&Gt_p, g_Gt);
        cudaGetSymbolAddress((void**)&beff_p, g_beff);
        cudaFuncSetAttribute(gemm_tf32,
                             cudaFuncAttributeMaxDynamicSharedMemorySize,
                             GSMEM_BYTES);
    }

    // 1. reset accumulators
    init_k<<<768, 256>>>();
    // 2. round Wkv to tf32
    rnd_k<<<(KVC * CDIM + 255) / 256, 256>>>(qkv_w);
    // 3. LayerNorm (tf32-rounded output)
    ln_k<<<RTOT, 256>>>(x, ln_w, ln_b);
    // 4. kv = xn @ Wkv^T + bkv   (tensor cores, tf32)
    gemm_tf32<<<dim3(KVC / 128, RTOT / 128, 1), 256, GSMEM_BYTES>>>(
        xn_p, wr_p, qkv_b + CDIM, kv_p,
        CDIM, CDIM, CDIM, KVC, 0, 0, 0, 0);
    // 5. softmax numerator + ctx accumulation (no max shift needed)
    ctx_k<<<dim3(BHN, 16), 256>>>();
    // 6. U_b = blockdiag(ctx_norm) applied to proj_w
    u_k<<<dim3(BHN, CDIM / 64), 256>>>(proj_w);
    // 7. effective bias
    beff_k<<<dim3(BATCH, CDIM / 256), 256>>>(qkv_b, proj_b);
    // 8. Gt_b[c3, c] = scale * sum_hd U_b[hd,c3] * Wq[hd,c]  (fp32 SIMT, round to tf32)
    gemm_tn<<<dim3(CDIM / 128, CDIM / 128, BATCH), 256>>>(
        U_p, qkv_w, Gt_p, CDIM, CDIM, CDIM, CDIM, SCALE,
        (long long)CDIM * CDIM, 0, (long long)CDIM * CDIM);
    // 9. final = xn[b] @ Gt_b^T + b_eff[b]   (tensor cores, tf32)
    gemm_tf32<<<dim3(CDIM / 128, NSEQ / 128, BATCH), 256, GSMEM_BYTES>>>(
        xn_p, Gt_p, beff_p, out,
        CDIM, CDIM, CDIM, CDIM,
        (long long)NSEQ * CDIM, (long long)CDIM * CDIM,
        (long long)NSEQ * CDIM, CDIM);
}

// round 8
// speedup vs baseline: 3.8977x; 1.3355x over previous
#include <cuda_runtime.h>
#include <cuda_fp16.h>
#include <cstdint>

// ---------------- problem constants ----------------
#define BATCH   4
#define NSEQ    8192
#define CDIM    768
#define HEADS   12
#define DHEAD   64
#define RTOT    (BATCH*NSEQ)      // 32768 rows
#define KVC     1536              // k||v feature dim
#define BHN     (BATCH*HEADS)     // 48
#define SCALE   0.125f            // D^-0.5
#define EPSLN   1e-5f

// ---------------- scratch (static device arrays; no runtime malloc) ----------------
__device__ __half g_xnh[RTOT*CDIM];      // layernormed x, fp16 (48 MB)
__device__ float  g_kv[RTOT*KVC];        // k||v projections (192 MB)
__device__ __half g_wrh[KVC*CDIM];       // fp16 Wkv
__device__ float  g_sumexp[BHN*DHEAD];   // softmax denominators
__device__ float  g_ctx[BHN*DHEAD*DHEAD];// sum exp(k)*v
__device__ float  g_U[BATCH*CDIM*CDIM];  // U_b[hd, c3]
__device__ __half g_Gth[BATCH*CDIM*CDIM];// Gt_b[c3out, c_in], fp16, incl. SCALE
__device__ float  g_beff[BATCH*CDIM];    // folded bias per batch

__device__ __forceinline__ void cp16(void* s, const void* g) {
    unsigned sa = (unsigned)__cvta_generic_to_shared(s);
    asm volatile("cp.async.cg.shared.global [%0], [%1], 16;\n" :: "r"(sa), "l"(g));
}
__device__ __forceinline__ uint32_t smem_u32(const void* p) {
    uint32_t a;
    asm("{ .reg .u64 t; cvta.to.shared.u64 t, %1; cvt.u32.u64 %0, t; }"
        : "=r"(a) : "l"(p));
    return a;
}
#define LDM4(r0, r1, r2, r3, addr)                                              \
    asm volatile("ldmatrix.sync.aligned.m8n8.x4.shared.b16 {%0,%1,%2,%3}, [%4];"\
                 : "=r"(r0), "=r"(r1), "=r"(r2), "=r"(r3) : "r"(addr))

// ---------------- init accumulators ----------------
__global__ void init_k() {
    int i = blockIdx.x * blockDim.x + threadIdx.x;
    if (i < BHN*DHEAD) g_sumexp[i] = 0.f;
    if (i < BHN*DHEAD*DHEAD) g_ctx[i] = 0.f;
}

// ---------------- round Wkv to fp16 ----------------
__global__ void rnd_k(const float* __restrict__ w) {
    int i = blockIdx.x * blockDim.x + threadIdx.x;
    if (i < KVC*CDIM) g_wrh[i] = __float2half_rn(w[CDIM*CDIM + i]);
}

// ---------------- LayerNorm: one block per row, fp16 output ----------------
__global__ __launch_bounds__(256) void ln_k(const float* __restrict__ x,
                                            const float* __restrict__ w,
                                            const float* __restrict__ b) {
    int row = blockIdx.x;
    int t = threadIdx.x;
    const float* xr = x + (long long)row * CDIM;
    float v0 = xr[t], v1 = xr[t + 256], v2 = xr[t + 512];
    float s  = v0 + v1 + v2;
    float ss = v0*v0 + v1*v1 + v2*v2;
    #pragma unroll
    for (int o = 16; o; o >>= 1) {
        s  += __shfl_xor_sync(0xffffffffu, s,  o);
        ss += __shfl_xor_sync(0xffffffffu, ss, o);
    }
    __shared__ float sh1[8], sh2[8];
    int wid = t >> 5, lid = t & 31;
    if (lid == 0) { sh1[wid] = s; sh2[wid] = ss; }
    __syncthreads();
    float ts = 0.f, tss = 0.f;
    #pragma unroll
    for (int i = 0; i < 8; i++) { ts += sh1[i]; tss += sh2[i]; }
    float mu   = ts * (1.f / CDIM);
    float var  = tss * (1.f / CDIM) - mu * mu;
    float rstd = rsqrtf(var + EPSLN);
    __half* o = g_xnh + (long long)row * CDIM;
    o[t]       = __float2half_rn((v0 - mu) * rstd * w[t]       + b[t]);
    o[t + 256] = __float2half_rn((v1 - mu) * rstd * w[t + 256] + b[t + 256]);
    o[t + 512] = __float2half_rn((v2 - mu) * rstd * w[t + 512] + b[t + 512]);
}

// ---------------- FP16 tensor-core GEMM (ldmatrix + mma.m16n8k16) ----------------
// A[m][k] row-major half (lda), B[n][k] row-major half (ldb),
// C[m][n] = sum_k A*B + bias[n] (fp32 accum/out).
// CTA tile 128x128, k-tile 32 halves (64B rows), 4-stage cp.async pipeline.
// Swizzle: 16B chunk' = chunk ^ ((row>>1)&3) -> conflict-free ldmatrix phases.
// M,N multiples of 128; K multiple of 32.
#define H_STAGES 4
#define H_STAGE_BYTES 8192                 // 128 rows x 64 B
#define H_SMEM_BYTES (2 * H_STAGES * H_STAGE_BYTES)   // 65536

__global__ __launch_bounds__(256, 2)
void gemm_h(const __half* __restrict__ A, const __half* __restrict__ B,
            const float* __restrict__ bias, float* __restrict__ C,
            int K, int lda, int ldb, int ldc,
            long long bsA, long long bsB, long long bsC, int bsBias) {
    extern __shared__ __align__(1024) unsigned char hsm[];
    const uint32_t sbA = smem_u32(hsm);
    const uint32_t sbB = sbA + H_STAGES * H_STAGE_BYTES;

    const int t = threadIdx.x;
    const int lane = t & 31, wid = t >> 5;
    const int n0 = blockIdx.x * 128, m0 = blockIdx.y * 128;
    const __half* Ab = A + (long long)blockIdx.z * bsA;
    const __half* Bb = B + (long long)blockIdx.z * bsB;
    float*        Cb = C + (long long)blockIdx.z * bsC;
    const float* biasb = bias + (long long)blockIdx.z * bsBias;

    const int wm = (wid >> 2) * 64, wn = (wid & 3) * 32;
    const int grp = lane >> 2, thr = lane & 3;

    // loader: thread t -> row t>>1, chunks {(t&1)*2, (t&1)*2+1} for A and B
    const int lr = t >> 1, lcp = (t & 1) << 1;

    float acc[4][4][4];
    #pragma unroll
    for (int i = 0; i < 4; i++)
        #pragma unroll
        for (int j = 0; j < 4; j++)
            #pragma unroll
            for (int q = 0; q < 4; q++) acc[i][j][q] = 0.f;

    #define H_LOAD(slot, k0)                                                    \
        do {                                                                    \
            _Pragma("unroll")                                                   \
            for (int c2 = 0; c2 < 2; c2++) {                                    \
                int ch = lcp + c2;                                              \
                int sw = lr * 64 + ((ch ^ ((lr >> 1) & 3)) << 4);               \
                cp16(hsm + (slot) * H_STAGE_BYTES + sw,                         \
                     Ab + (long long)(m0 + lr) * lda + (k0) + ch * 8);          \
                cp16(hsm + (H_STAGES + (slot)) * H_STAGE_BYTES + sw,            \
                     Bb + (long long)(n0 + lr) * ldb + (k0) + ch * 8);          \
            }                                                                   \
            asm volatile("cp.async.commit_group;\n");                           \
        } while (0)

    const int T = K >> 5;   // K / 32
    H_LOAD(0, 0);
    H_LOAD(1, 32);
    H_LOAD(2, 64);

    // precomputed fragment rows (lane-dependent)
    const int arow = (lane & 15);                       // A: row within m16
    const int brow = (lane & 7) + ((lane >> 4) << 3);   // B: row within n16
    const int acs  = lane >> 4;                         // A: chunk select 0/1
    const int bcs  = (lane >> 3) & 1;                   // B: chunk select 0/1

    for (int tt = 0; tt < T; tt++) {
        asm volatile("cp.async.wait_group 2;\n" ::: "memory");
        __syncthreads();
        if (tt + 3 < T) {
            H_LOAD((tt + 3) & (H_STAGES - 1), (tt + 3) << 5);
        } else {
            asm volatile("cp.async.commit_group;\n");
        }
        const int slot = tt & (H_STAGES - 1);
        const uint32_t aBase = sbA + slot * H_STAGE_BYTES;
        const uint32_t bBase = sbB + slot * H_STAGE_BYTES;
        #pragma unroll
        for (int kk = 0; kk < 32; kk += 16) {
            uint32_t a[4][4], b[2][4];
            #pragma unroll
            for (int mi = 0; mi < 4; mi++) {
                int row = wm + mi * 16 + arow;
                int ch = (kk >> 3) + acs;
                uint32_t ad = aBase + row * 64 + ((ch ^ ((row >> 1) & 3)) << 4);
                LDM4(a[mi][0], a[mi][1], a[mi][2], a[mi][3], ad);
            }
            #pragma unroll
            for (int njp = 0; njp < 2; njp++) {
                int row = wn + njp * 16 + brow;
                int ch = (kk >> 3) + bcs;
                uint32_t bd = bBase + row * 64 + ((ch ^ ((row >> 1) & 3)) << 4);
                LDM4(b[njp][0], b[njp][1], b[njp][2], b[njp][3], bd);
            }
            #pragma unroll
            for (int mi = 0; mi < 4; mi++)
                #pragma unroll
                for (int nj = 0; nj < 4; nj++)
                    asm volatile(
                        "mma.sync.aligned.m16n8k16.row.col.f32.f16.f16.f32 "
                        "{%0,%1,%2,%3}, {%4,%5,%6,%7}, {%8,%9}, {%0,%1,%2,%3};\n"
                        : "+f"(acc[mi][nj][0]), "+f"(acc[mi][nj][1]),
                          "+f"(acc[mi][nj][2]), "+f"(acc[mi][nj][3])
                        : "r"(a[mi][0]), "r"(a[mi][1]), "r"(a[mi][2]), "r"(a[mi][3]),
                          "r"(b[nj >> 1][(nj & 1) * 2]),
                          "r"(b[nj >> 1][(nj & 1) * 2 + 1]));
        }
        __syncthreads();
    }
    #undef H_LOAD

    #pragma unroll
    for (int mi = 0; mi < 4; mi++) {
        #pragma unroll
        for (int nj = 0; nj < 4; nj++) {
            int m = m0 + wm + mi * 16 + grp;
            int n = n0 + wn + nj * 8 + 2 * thr;
            float bi0 = biasb[n], bi1 = biasb[n + 1];
            float2 v0 = make_float2(acc[mi][nj][0] + bi0, acc[mi][nj][1] + bi1);
            float2 v1 = make_float2(acc[mi][nj][2] + bi0, acc[mi][nj][3] + bi1);
            *(float2*)&Cb[(long long)m * ldc + n] = v0;
            *(float2*)&Cb[(long long)(m + 8) * ldc + n] = v1;
        }
    }
}

// ---------------- fp32 SIMT GEMM (small compose step), fp16 output ----------------
// A[k*lda + m], B[k*ldb + n], C[m*ldc+n] = half(alpha * sum)
__global__ __launch_bounds__(256)
void gemm_tn(const float* __restrict__ A, const float* __restrict__ B,
             __half* __restrict__ C, int K, int lda, int ldb, int ldc,
             float alpha, long long bsA, long long bsB, long long bsC) {
    __shared__ float As[8][132];
    __shared__ float Bs[8][132];
    int t = threadIdx.x;
    int tx = t & 15, ty = t >> 4;
    int n0 = blockIdx.x * 128;
    int m0 = blockIdx.y * 128;
    const float* Ab = A + (long long)blockIdx.z * bsA;
    const float* Bb = B + (long long)blockIdx.z * bsB;
    __half*      Cb = C + (long long)blockIdx.z * bsC;

    float acc[8][8];
    #pragma unroll
    for (int i = 0; i < 8; i++)
        #pragma unroll
        for (int j = 0; j < 8; j++) acc[i][j] = 0.f;

    for (int k0 = 0; k0 < K; k0 += 8) {
        {
            int k = t >> 5, mq = (t & 31) * 4;
            *(float4*)&As[k][mq] =
                *(const float4*)&Ab[(long long)(k0 + k) * lda + m0 + mq];
            *(float4*)&Bs[k][mq] =
                *(const float4*)&Bb[(long long)(k0 + k) * ldb + n0 + mq];
        }
        __syncthreads();
        #pragma unroll
        for (int k = 0; k < 8; k++) {
            float4 a0 = *(float4*)&As[k][ty * 8];
            float4 a1 = *(float4*)&As[k][ty * 8 + 4];
            float4 b0 = *(float4*)&Bs[k][tx * 8];
            float4 b1 = *(float4*)&Bs[k][tx * 8 + 4];
            float av[8] = {a0.x, a0.y, a0.z, a0.w, a1.x, a1.y, a1.z, a1.w};
            float bv[8] = {b0.x, b0.y, b0.z, b0.w, b1.x, b1.y, b1.z, b1.w};
            #pragma unroll
            for (int i = 0; i < 8; i++)
                #pragma unroll
                for (int j = 0; j < 8; j++)
                    acc[i][j] += av[i] * bv[j];
        }
        __syncthreads();
    }
    #pragma unroll
    for (int i = 0; i < 8; i++) {
        int m = m0 + ty * 8 + i;
        #pragma unroll
        for (int j = 0; j < 8; j += 2) {
            int n = n0 + tx * 8 + j;
            __half2 h = __floats2half2_rn(alpha * acc[i][j], alpha * acc[i][j + 1]);
            *(__half2*)&Cb[(long long)m * ldc + n] = h;
        }
    }
}

// ---------------- fused softmax-numerator + ctx accumulation (no max shift) ----------------
__global__ __launch_bounds__(256) void ctx_k() {
    int bh = blockIdx.x, ch = blockIdx.y;
    int b = bh / HEADS, h = bh - b * HEADS;
    int t = threadIdx.x;
    __shared__ float sk[8][64];
    __shared__ float sv[8][64];
    float acc[4][4];
    #pragma unroll
    for (int i = 0; i < 4; i++)
        #pragma unroll
        for (int j = 0; j < 4; j++) acc[i][j] = 0.f;
    float seloc = 0.f;
    int d0 = (t & 15) * 4, e0 = (t >> 4) * 4;
    int dmy = t & 63;
    long long rowb = ((long long)b * NSEQ + ch * 512) * KVC + h * 64;
    for (int tile = 0; tile < 64; tile++) {
        #pragma unroll
        for (int i = 0; i < 4; i++) {
            int f = t + i * 256;
            int r = f >> 7, c = f & 127;
            float v = g_kv[rowb + (long long)(tile * 8 + r) * KVC +
                           (c < 64 ? c : 704 + c)];
            if (c < 64) sk[r][c] = v; else sv[r][c - 64] = v;
        }
        __syncthreads();
        {
            int r = t >> 6;
            float e1 = __expf(sk[r][dmy]);
            sk[r][dmy] = e1; seloc += e1;
            r += 4;
            float e2 = __expf(sk[r][dmy]);
            sk[r][dmy] = e2; seloc += e2;
        }
        __syncthreads();
        #pragma unroll
        for (int r = 0; r < 8; r++) {
            float4 a  = *(float4*)&sk[r][d0];
            float4 bb = *(float4*)&sv[r][e0];
            float av[4] = {a.x, a.y, a.z, a.w};
            float bv[4] = {bb.x, bb.y, bb.z, bb.w};
            #pragma unroll
            for (int i = 0; i < 4; i++)
                #pragma unroll
                for (int j = 0; j < 4; j++) acc[i][j] += av[i] * bv[j];
        }
        __syncthreads();
    }
    __shared__ float ssum[256];
    ssum[t] = seloc;
    __syncthreads();
    if (t < 64)
        atomicAdd(&g_sumexp[bh * 64 + t],
                  ssum[t] + ssum[t + 64] + ssum[t + 128] + ssum[t + 192]);
    float* cb = &g_ctx[bh * 4096];
    #pragma unroll
    for (int i = 0; i < 4; i++)
        #pragma unroll
        for (int j = 0; j < 4; j++)
            atomicAdd(&cb[(d0 + i) * 64 + (e0 + j)], acc[i][j]);
}

// ---------------- U_b[h*64+d, c3] = sum_e (ctx[d,e]/sumexp[d]) * proj_w[c3, h*64+e] ----------------
__global__ __launch_bounds__(256) void u_k(const float* __restrict__ pw) {
    int bh = blockIdx.x;
    int c30 = blockIdx.y * 64;
    int b = bh / HEADS, h = bh - b * HEADS;
    int t = threadIdx.x;
    __shared__ float inv[64];
    __shared__ float sce[64][68];  // [e][d]
    __shared__ float spw[64][68];  // [e][c3_local]
    if (t < 64) inv[t] = 1.f / g_sumexp[bh * 64 + t];
    __syncthreads();
    #pragma unroll
    for (int i = 0; i < 16; i++) {
        int idx = t + i * 256;
        int d = idx >> 6, e = idx & 63;
        sce[e][d] = g_ctx[bh * 4096 + idx] * inv[d];
    }
    #pragma unroll
    for (int i = 0; i < 16; i++) {
        int idx = t + i * 256;
        int c3l = idx >> 6, e = idx & 63;
        spw[e][c3l] = pw[(long long)(c30 + c3l) * CDIM + h * 64 + e];
    }
    __syncthreads();
    int d0 = (t & 15) * 4, c0 = (t >> 4) * 4;
    float acc[4][4];
    #pragma unroll
    for (int i = 0; i < 4; i++)
        #pragma unroll
        for (int j = 0; j < 4; j++) acc[i][j] = 0.f;
    #pragma unroll 8
    for (int e = 0; e < 64; e++) {
        float4 a  = *(float4*)&sce[e][d0];
        float4 bb = *(float4*)&spw[e][c0];
        float av[4] = {a.x, a.y, a.z, a.w};
        float bv[4] = {bb.x, bb.y, bb.z, bb.w};
        #pragma unroll
        for (int i = 0; i < 4; i++)
            #pragma unroll
            for (int j = 0; j < 4; j++) acc[i][j] += av[i] * bv[j];
    }
    float* Ub = &g_U[(long long)b * CDIM * CDIM];
    #pragma unroll
    for (int i = 0; i < 4; i++)
        #pragma unroll
        for (int j = 0; j < 4; j++)
            Ub[(long long)(h * 64 + d0 + i) * CDIM + c30 + c0 + j] = acc[i][j];
}

// ---------------- b_eff[b][c3] = scale * sum_hd qkv_b[hd]*U_b[hd,c3] + proj_b[c3] ----------------
__global__ __launch_bounds__(256) void beff_k(const float* __restrict__ qb,
                                              const float* __restrict__ pb) {
    int b = blockIdx.x;
    int c3 = blockIdx.y * 256 + threadIdx.x;
    const float* Ub = &g_U[(long long)b * CDIM * CDIM];
    float acc = pb[c3];
    #pragma unroll 8
    for (int hd = 0; hd < CDIM; hd++)
        acc += SCALE * qb[hd] * Ub[(long long)hd * CDIM + c3];
    g_beff[b * CDIM + c3] = acc;
}

// ---------------- launch ----------------
extern "C" void kernel_launch(void* const* d_in, const int* in_sizes, int n_in,
                              void* d_out, int out_size) {
    const float* x      = (const float*)d_in[0];
    const float* ln_w   = (const float*)d_in[1];
    const float* ln_b   = (const float*)d_in[2];
    const float* qkv_w  = (const float*)d_in[3];
    const float* qkv_b  = (const float*)d_in[4];
    const float* proj_w = (const float*)d_in[5];
    const float* proj_b = (const float*)d_in[6];
    float* out = (float*)d_out;

    static __half* xnh_p = nullptr;
    static float*  kv_p = nullptr;
    static __half* wrh_p = nullptr;
    static float*  U_p = nullptr;
    static __half* Gth_p = nullptr;
    static float*  beff_p = nullptr;
    if (!xnh_p) {
        cudaGetSymbolAddress((void**)&xnh_p, g_xnh);
        cudaGetSymbolAddress((void**)&kv_p, g_kv);
        cudaGetSymbolAddress((void**)&wrh_p, g_wrh);
        cudaGetSymbolAddress((void**)&U_p, g_U);
        cudaGetSymbolAddress((void**)&Gth_p, g_Gth);
        cudaGetSymbolAddress((void**)&beff_p, g_beff);
        cudaFuncSetAttribute(gemm_h,
                             cudaFuncAttributeMaxDynamicSharedMemorySize,
                             H_SMEM_BYTES);
    }

    // 1. reset accumulators
    init_k<<<768, 256>>>();
    // 2. Wkv -> fp16
    rnd_k<<<(KVC * CDIM + 255) / 256, 256>>>(qkv_w);
    // 3. LayerNorm (fp16 output)
    ln_k<<<RTOT, 256>>>(x, ln_w, ln_b);
    // 4. kv = xn @ Wkv^T + bkv   (fp16 tensor cores)
    gemm_h<<<dim3(KVC / 128, RTOT / 128, 1), 256, H_SMEM_BYTES>>>(
        xnh_p, wrh_p, qkv_b + CDIM, kv_p,
        CDIM, CDIM, CDIM, KVC, 0, 0, 0, 0);
    // 5. softmax numerator + ctx accumulation (no max shift needed)
    ctx_k<<<dim3(BHN, 16), 256>>>();
    // 6. U_b = blockdiag(ctx_norm) applied to proj_w
    u_k<<<dim3(BHN, CDIM / 64), 256>>>(proj_w);
    // 7. effective bias
    beff_k<<<dim3(BATCH, CDIM / 256), 256>>>(qkv_b, proj_b);
    // 8. Gt_b[c3out, c_in] = scale * sum_hd U_b[hd,c3out] * Wq[hd,c_in]  (fp32 SIMT -> fp16)
    gemm_tn<<<dim3(CDIM / 128, CDIM / 128, BATCH), 256>>>(
        U_p, qkv_w, Gth_p, CDIM, CDIM, CDIM, CDIM, SCALE,
        (long long)CDIM * CDIM, 0, (long long)CDIM * CDIM);
    // 9. final = xn[b] @ Gt_b^T + b_eff[b]   (fp16 tensor cores)
    gemm_h<<<dim3(CDIM / 128, NSEQ / 128, BATCH), 256, H_SMEM_BYTES>>>(
        xnh_p, Gth_p, beff_p, out,
        CDIM, CDIM, CDIM, CDIM,
        (long long)NSEQ * CDIM, (long long)CDIM * CDIM,
        (long long)NSEQ * CDIM, CDIM);
}

// round 10
// speedup vs baseline: 4.1291x; 1.0593x over previous
#include <cuda_runtime.h>
#include <cuda_fp16.h>
#include <cstdint>

// ---------------- problem constants ----------------
#define BATCH   4
#define NSEQ    8192
#define CDIM    768
#define HEADS   12
#define DHEAD   64
#define RTOT    (BATCH*NSEQ)      // 32768 rows
#define KVC     1536              // k||v feature dim
#define BHN     (BATCH*HEADS)     // 48
#define SCALE   0.125f            // D^-0.5
#define EPSLN   1e-5f
#define CC      (CDIM*CDIM)

// ---------------- scratch (static device arrays; no runtime malloc) ----------------
__device__ __half g_xnh[RTOT*CDIM];      // layernormed x, fp16 (48 MB)
__device__ __half g_kvh[RTOT*KVC];       // k||v projections, fp16 (96 MB)
__device__ __half g_wrh[KVC*CDIM];       // fp16 Wkv
__device__ __half g_wqth[CC];            // fp16 Wq^T  [c][hd]
__device__ float  g_sumexp[BHN*DHEAD];   // softmax denominators
__device__ float  g_ctx[BHN*DHEAD*DHEAD];// sum exp(k)*v
__device__ __half g_uth[BATCH*CC];       // U^T_b [c3][hd], fp16
__device__ __half g_gth[BATCH*CC];       // Gt_b [c3][c], fp16 (incl. SCALE)
__device__ float  g_beff[BATCH*CDIM];    // folded bias per batch
__device__ float  g_zerob[CDIM];         // zero bias (never written -> stays 0)

__device__ __forceinline__ void cp16(void* s, const void* g) {
    unsigned sa = (unsigned)__cvta_generic_to_shared(s);
    asm volatile("cp.async.cg.shared.global [%0], [%1], 16;\n" :: "r"(sa), "l"(g));
}
__device__ __forceinline__ uint32_t smem_u32(const void* p) {
    uint32_t a;
    asm("{ .reg .u64 t; cvta.to.shared.u64 t, %1; cvt.u32.u64 %0, t; }"
        : "=r"(a) : "l"(p));
    return a;
}
#define LDM4(r0, r1, r2, r3, addr)                                              \
    asm volatile("ldmatrix.sync.aligned.m8n8.x4.shared.b16 {%0,%1,%2,%3}, [%4];"\
                 : "=r"(r0), "=r"(r1), "=r"(r2), "=r"(r3) : "r"(addr))

// ---------------- init accumulators ----------------
__global__ void init_k() {
    int i = blockIdx.x * blockDim.x + threadIdx.x;
    if (i < BHN*DHEAD) g_sumexp[i] = 0.f;
    if (i < BHN*DHEAD*DHEAD) g_ctx[i] = 0.f;
}

// ---------------- Wkv -> fp16 ; Wq -> fp16 transposed ----------------
__global__ void rnd_k(const float* __restrict__ w) {
    int i = blockIdx.x * blockDim.x + threadIdx.x;
    if (i < KVC*CDIM) g_wrh[i] = __float2half_rn(w[CC + i]);
    if (i < CC) {
        int hd = i / CDIM, c = i - hd * CDIM;
        g_wqth[c * CDIM + hd] = __float2half_rn(w[i]);
    }
}

// ---------------- LayerNorm: one block per row, fp16 output ----------------
__global__ __launch_bounds__(256) void ln_k(const float* __restrict__ x,
                                            const float* __restrict__ w,
                                            const float* __restrict__ b) {
    int row = blockIdx.x;
    int t = threadIdx.x;
    const float* xr = x + (long long)row * CDIM;
    float v0 = xr[t], v1 = xr[t + 256], v2 = xr[t + 512];
    float s  = v0 + v1 + v2;
    float ss = v0*v0 + v1*v1 + v2*v2;
    #pragma unroll
    for (int o = 16; o; o >>= 1) {
        s  += __shfl_xor_sync(0xffffffffu, s,  o);
        ss += __shfl_xor_sync(0xffffffffu, ss, o);
    }
    __shared__ float sh1[8], sh2[8];
    int wid = t >> 5, lid = t & 31;
    if (lid == 0) { sh1[wid] = s; sh2[wid] = ss; }
    __syncthreads();
    float ts = 0.f, tss = 0.f;
    #pragma unroll
    for (int i = 0; i < 8; i++) { ts += sh1[i]; tss += sh2[i]; }
    float mu   = ts * (1.f / CDIM);
    float var  = tss * (1.f / CDIM) - mu * mu;
    float rstd = rsqrtf(var + EPSLN);
    __half* o = g_xnh + (long long)row * CDIM;
    o[t]       = __float2half_rn((v0 - mu) * rstd * w[t]       + b[t]);
    o[t + 256] = __float2half_rn((v1 - mu) * rstd * w[t + 256] + b[t + 256]);
    o[t + 512] = __float2half_rn((v2 - mu) * rstd * w[t + 512] + b[t + 512]);
}

// ---------------- FP16 tensor-core GEMM (ldmatrix + mma.m16n8k16) ----------------
// A[m][k] row-major half (lda), B[n][k] row-major half (ldb),
// C[m][n] = alpha * sum_k A*B + bias[n]  (fp32 accum; OutT = float or __half).
// CTA tile 128x128, k-tile 32 halves (64B rows), 4-stage cp.async pipeline,
// ONE barrier per mainloop iteration.
#define H_STAGES 4
#define H_STAGE_BYTES 8192                 // 128 rows x 64 B
#define H_SMEM_BYTES (2 * H_STAGES * H_STAGE_BYTES)   // 65536

template <typename OutT>
__global__ __launch_bounds__(256, 2)
void gemm_h(const __half* __restrict__ A, const __half* __restrict__ B,
            const float* __restrict__ bias, OutT* __restrict__ C,
            int K, int lda, int ldb, int ldc, float alpha,
            long long bsA, long long bsB, long long bsC, int bsBias) {
    extern __shared__ __align__(1024) unsigned char hsm[];
    const uint32_t sbA = smem_u32(hsm);
    const uint32_t sbB = sbA + H_STAGES * H_STAGE_BYTES;

    const int t = threadIdx.x;
    const int lane = t & 31, wid = t >> 5;
    const int n0 = blockIdx.x * 128, m0 = blockIdx.y * 128;
    const __half* Ab = A + (long long)blockIdx.z * bsA;
    const __half* Bb = B + (long long)blockIdx.z * bsB;
    OutT*         Cb = C + (long long)blockIdx.z * bsC;
    const float* biasb = bias + (long long)blockIdx.z * bsBias;

    const int wm = (wid >> 2) * 64, wn = (wid & 3) * 32;
    const int grp = lane >> 2, thr = lane & 3;

    // loader: thread t -> row t>>1, chunks {(t&1)*2, (t&1)*2+1} for A and B
    const int lr = t >> 1, lcp = (t & 1) << 1;

    float acc[4][4][4];
    #pragma unroll
    for (int i = 0; i < 4; i++)
        #pragma unroll
        for (int j = 0; j < 4; j++)
            #pragma unroll
            for (int q = 0; q < 4; q++) acc[i][j][q] = 0.f;

    #define H_LOAD(slot, k0)                                                    \
        do {                                                                    \
            _Pragma("unroll")                                                   \
            for (int c2 = 0; c2 < 2; c2++) {                                    \
                int ch = lcp + c2;                                              \
                int sw = lr * 64 + ((ch ^ ((lr >> 1) & 3)) << 4);               \
                cp16(hsm + (slot) * H_STAGE_BYTES + sw,                         \
                     Ab + (long long)(m0 + lr) * lda + (k0) + ch * 8);          \
                cp16(hsm + (H_STAGES + (slot)) * H_STAGE_BYTES + sw,            \
                     Bb + (long long)(n0 + lr) * ldb + (k0) + ch * 8);          \
            }                                                                   \
            asm volatile("cp.async.commit_group;\n");                           \
        } while (0)

    const int T = K >> 5;   // K / 32
    H_LOAD(0, 0);
    H_LOAD(1, 32);
    H_LOAD(2, 64);

    // precomputed fragment rows (lane-dependent)
    const int arow = (lane & 15);                       // A: row within m16
    const int brow = (lane & 7) + ((lane >> 4) << 3);   // B: row within n16
    const int acs  = lane >> 4;                         // A: chunk select 0/1
    const int bcs  = (lane >> 3) & 1;                   // B: chunk select 0/1

    for (int tt = 0; tt < T; tt++) {
        asm volatile("cp.async.wait_group 2;\n" ::: "memory");
        __syncthreads();   // single barrier: orders slot reuse AND data ready
        if (tt + 3 < T) {
            H_LOAD((tt + 3) & (H_STAGES - 1), (tt + 3) << 5);
        } else {
            asm volatile("cp.async.commit_group;\n");
        }
        const int slot = tt & (H_STAGES - 1);
        const uint32_t aBase = sbA + slot * H_STAGE_BYTES;
        const uint32_t bBase = sbB + slot * H_STAGE_BYTES;
        #pragma unroll
        for (int kk = 0; kk < 32; kk += 16) {
            uint32_t a[4][4], b[2][4];
            #pragma unroll
            for (int mi = 0; mi < 4; mi++) {
                int row = wm + mi * 16 + arow;
                int ch = (kk >> 3) + acs;
                uint32_t ad = aBase + row * 64 + ((ch ^ ((row >> 1) & 3)) << 4);
                LDM4(a[mi][0], a[mi][1], a[mi][2], a[mi][3], ad);
            }
            #pragma unroll
            for (int njp = 0; njp < 2; njp++) {
                int row = wn + njp * 16 + brow;
                int ch = (kk >> 3) + bcs;
                uint32_t bd = bBase + row * 64 + ((ch ^ ((row >> 1) & 3)) << 4);
                LDM4(b[njp][0], b[njp][1], b[njp][2], b[njp][3], bd);
            }
            #pragma unroll
            for (int mi = 0; mi < 4; mi++)
                #pragma unroll
                for (int nj = 0; nj < 4; nj++)
                    asm volatile(
                        "mma.sync.aligned.m16n8k16.row.col.f32.f16.f16.f32 "
                        "{%0,%1,%2,%3}, {%4,%5,%6,%7}, {%8,%9}, {%0,%1,%2,%3};\n"
                        : "+f"(acc[mi][nj][0]), "+f"(acc[mi][nj][1]),
                          "+f"(acc[mi][nj][2]), "+f"(acc[mi][nj][3])
                        : "r"(a[mi][0]), "r"(a[mi][1]), "r"(a[mi][2]), "r"(a[mi][3]),
                          "r"(b[nj >> 1][(nj & 1) * 2]),
                          "r"(b[nj >> 1][(nj & 1) * 2 + 1]));
        }
    }
    #undef H_LOAD

    #pragma unroll
    for (int mi = 0; mi < 4; mi++) {
        #pragma unroll
        for (int nj = 0; nj < 4; nj++) {
            int m = m0 + wm + mi * 16 + grp;
            int n = n0 + wn + nj * 8 + 2 * thr;
            float bi0 = biasb[n], bi1 = biasb[n + 1];
            float o00 = alpha * acc[mi][nj][0] + bi0;
            float o01 = alpha * acc[mi][nj][1] + bi1;
            float o10 = alpha * acc[mi][nj][2] + bi0;
            float o11 = alpha * acc[mi][nj][3] + bi1;
            if constexpr (sizeof(OutT) == 4) {
                *(float2*)&Cb[(long long)m * ldc + n] = make_float2(o00, o01);
                *(float2*)&Cb[(long long)(m + 8) * ldc + n] = make_float2(o10, o11);
            } else {
                *(__half2*)&Cb[(long long)m * ldc + n] = __floats2half2_rn(o00, o01);
                *(__half2*)&Cb[(long long)(m + 8) * ldc + n] = __floats2half2_rn(o10, o11);
            }
        }
    }
}

// ---------------- fused softmax-numerator + ctx accumulation (no max shift) ----------------
__global__ __launch_bounds__(256) void ctx_k() {
    int bh = blockIdx.x, ch = blockIdx.y;
    int b = bh / HEADS, h = bh - b * HEADS;
    int t = threadIdx.x;
    __shared__ float sk[8][64];
    __shared__ float sv[8][64];
    float acc[4][4];
    #pragma unroll
    for (int i = 0; i < 4; i++)
        #pragma unroll
        for (int j = 0; j < 4; j++) acc[i][j] = 0.f;
    float seloc = 0.f;
    int d0 = (t & 15) * 4, e0 = (t >> 4) * 4;
    int dmy = t & 63;
    long long rowb = ((long long)b * NSEQ + ch * 512) * KVC + h * 64;
    for (int tile = 0; tile < 64; tile++) {
        #pragma unroll
        for (int i = 0; i < 4; i++) {
            int f = t + i * 256;
            int r = f >> 7, c = f & 127;
            float v = __half2float(g_kvh[rowb + (long long)(tile * 8 + r) * KVC +
                                         (c < 64 ? c : 704 + c)]);
            if (c < 64) sk[r][c] = v; else sv[r][c - 64] = v;
        }
        __syncthreads();
        {
            int r = t >> 6;
            float e1 = __expf(sk[r][dmy]);
            sk[r][dmy] = e1; seloc += e1;
            r += 4;
            float e2 = __expf(sk[r][dmy]);
            sk[r][dmy] = e2; seloc += e2;
        }
        __syncthreads();
        #pragma unroll
        for (int r = 0; r < 8; r++) {
            float4 a  = *(float4*)&sk[r][d0];
            float4 bb = *(float4*)&sv[r][e0];
            float av[4] = {a.x, a.y, a.z, a.w};
            float bv[4] = {bb.x, bb.y, bb.z, bb.w};
            #pragma unroll
            for (int i = 0; i < 4; i++)
                #pragma unroll
                for (int j = 0; j < 4; j++) acc[i][j] += av[i] * bv[j];
        }
        __syncthreads();
    }
    __shared__ float ssum[256];
    ssum[t] = seloc;
    __syncthreads();
    if (t < 64)
        atomicAdd(&g_sumexp[bh * 64 + t],
                  ssum[t] + ssum[t + 64] + ssum[t + 128] + ssum[t + 192]);
    float* cb = &g_ctx[bh * 4096];
    #pragma unroll
    for (int i = 0; i < 4; i++)
        #pragma unroll
        for (int j = 0; j < 4; j++)
            atomicAdd(&cb[(d0 + i) * 64 + (e0 + j)], acc[i][j]);
}

// ---------------- U^T_b[c3][h*64+d] = sum_e (ctx[d,e]/sumexp[d]) * proj_w[c3, h*64+e] ----------------
__global__ __launch_bounds__(256) void u_k(const float* __restrict__ pw) {
    int bh = blockIdx.x;
    int c30 = blockIdx.y * 64;
    int b = bh / HEADS, h = bh - b * HEADS;
    int t = threadIdx.x;
    __shared__ float inv[64];
    __shared__ float sce[64][68];  // [e][d]
    __shared__ float spw[64][68];  // [e][c3_local]
    if (t < 64) inv[t] = 1.f / g_sumexp[bh * 64 + t];
    __syncthreads();
    #pragma unroll
    for (int i = 0; i < 16; i++) {
        int idx = t + i * 256;
        int d = idx >> 6, e = idx & 63;
        sce[e][d] = g_ctx[bh * 4096 + idx] * inv[d];
    }
    #pragma unroll
    for (int i = 0; i < 16; i++) {
        int idx = t + i * 256;
        int c3l = idx >> 6, e = idx & 63;
        spw[e][c3l] = pw[(long long)(c30 + c3l) * CDIM + h * 64 + e];
    }
    __syncthreads();
    int d0 = (t & 15) * 4, c0 = (t >> 4) * 4;
    float acc[4][4];
    #pragma unroll
    for (int i = 0; i < 4; i++)
        #pragma unroll
        for (int j = 0; j < 4; j++) acc[i][j] = 0.f;
    #pragma unroll 8
    for (int e = 0; e < 64; e++) {
        float4 a  = *(float4*)&sce[e][d0];
        float4 bb = *(float4*)&spw[e][c0];
        float av[4] = {a.x, a.y, a.z, a.w};
        float bv[4] = {bb.x, bb.y, bb.z, bb.w};
        #pragma unroll
        for (int i = 0; i < 4; i++)
            #pragma unroll
            for (int j = 0; j < 4; j++) acc[i][j] += av[i] * bv[j];
    }
    __half* Ut = &g_uth[(long long)b * CC];
    #pragma unroll
    for (int i = 0; i < 4; i++)
        #pragma unroll
        for (int j = 0; j < 4; j++)
            Ut[(long long)(c30 + c0 + j) * CDIM + h * 64 + d0 + i] =
                __float2half_rn(acc[i][j]);
}

// ---------------- b_eff[b][c3] = scale * sum_hd qkv_b[hd]*U^T[c3][hd] + proj_b[c3] ----------------
__global__ __launch_bounds__(256) void beff_k(const float* __restrict__ qb,
                                              const float* __restrict__ pb) {
    int b = blockIdx.x;
    int c3 = blockIdx.y * 256 + threadIdx.x;
    const __half* Ut = &g_uth[(long long)b * CC + (long long)c3 * CDIM];
    float acc = pb[c3];
    #pragma unroll 8
    for (int hd = 0; hd < CDIM; hd++)
        acc += SCALE * qb[hd] * __half2float(Ut[hd]);
    g_beff[b * CDIM + c3] = acc;
}

// ---------------- launch ----------------
extern "C" void kernel_launch(void* const* d_in, const int* in_sizes, int n_in,
                              void* d_out, int out_size) {
    const float* x      = (const float*)d_in[0];
    const float* ln_w   = (const float*)d_in[1];
    const float* ln_b   = (const float*)d_in[2];
    const float* qkv_w  = (const float*)d_in[3];
    const float* qkv_b  = (const float*)d_in[4];
    const float* proj_w = (const float*)d_in[5];
    const float* proj_b = (const float*)d_in[6];
    float* out = (float*)d_out;

    static __half* xnh_p = nullptr;
    static __half* kvh_p = nullptr;
    static __half* wrh_p = nullptr;
    static __half* wqth_p = nullptr;
    static __half* uth_p = nullptr;
    static __half* gth_p = nullptr;
    static float*  beff_p = nullptr;
    static float*  zerob_p = nullptr;
    if (!xnh_p) {
        cudaGetSymbolAddress((void**)&xnh_p, g_xnh);
        cudaGetSymbolAddress((void**)&kvh_p, g_kvh);
        cudaGetSymbolAddress((void**)&wrh_p, g_wrh);
        cudaGetSymbolAddress((void**)&wqth_p, g_wqth);
        cudaGetSymbolAddress((void**)&uth_p, g_uth);
        cudaGetSymbolAddress((void**)&gth_p, g_gth);
        cudaGetSymbolAddress((void**)&beff_p, g_beff);
        cudaGetSymbolAddress((void**)&zerob_p, g_zerob);
        cudaFuncSetAttribute(gemm_h<__half>,
                             cudaFuncAttributeMaxDynamicSharedMemorySize,
                             H_SMEM_BYTES);
        cudaFuncSetAttribute(gemm_h<float>,
                             cudaFuncAttributeMaxDynamicSharedMemorySize,
                             H_SMEM_BYTES);
    }

    // 1. reset accumulators
    init_k<<<768, 256>>>();
    // 2. weights -> fp16 (Wkv rows, Wq transposed)
    rnd_k<<<(KVC * CDIM + 255) / 256, 256>>>(qkv_w);
    // 3. LayerNorm (fp16 output)
    ln_k<<<RTOT, 256>>>(x, ln_w, ln_b);
    // 4. kv = xn @ Wkv^T + bkv   (fp16 tensor cores, fp16 output)
    gemm_h<__half><<<dim3(KVC / 128, RTOT / 128, 1), 256, H_SMEM_BYTES>>>(
        xnh_p, wrh_p, qkv_b + CDIM, kvh_p,
        CDIM, CDIM, CDIM, KVC, 1.f, 0, 0, 0, 0);
    // 5. softmax numerator + ctx accumulation
    ctx_k<<<dim3(BHN, 16), 256>>>();
    // 6. U^T_b (fp16) = blockdiag(ctx_norm) applied to proj_w
    u_k<<<dim3(BHN, CDIM / 64), 256>>>(proj_w);
    // 7. effective bias
    beff_k<<<dim3(BATCH, CDIM / 256), 256>>>(qkv_b, proj_b);
    // 8. Gt_b[c3][c] = SCALE * U^T_b @ Wq^T^T   (fp16 tensor cores)
    gemm_h<__half><<<dim3(CDIM / 128, CDIM / 128, BATCH), 256, H_SMEM_BYTES>>>(
        uth_p, wqth_p, zerob_p, gth_p,
        CDIM, CDIM, CDIM, CDIM, SCALE,
        (long long)CC, 0, (long long)CC, 0);
    // 9. final = xn[b] @ Gt_b^T + b_eff[b]   (fp16 tensor cores, fp32 output)
    gemm_h<float><<<dim3(CDIM / 128, NSEQ / 128, BATCH), 256, H_SMEM_BYTES>>>(
        xnh_p, gth_p, beff_p, out,
        CDIM, CDIM, CDIM, CDIM, 1.f,
        (long long)NSEQ * CDIM, (long long)CC,
        (long long)NSEQ * CDIM, CDIM);
}

// round 11
// speedup vs baseline: 4.8923x; 1.1848x over previous
#include <cuda_runtime.h>
#include <cuda_fp16.h>
#include <cstdint>

// ---------------- problem constants ----------------
#define BATCH   4
#define NSEQ    8192
#define CDIM    768
#define HEADS   12
#define DHEAD   64
#define RTOT    (BATCH*NSEQ)      // 32768 rows
#define KVC     1536              // k||v feature dim
#define BHN     (BATCH*HEADS)     // 48
#define SCALE   0.125f            // D^-0.5
#define EPSLN   1e-5f
#define CC      (CDIM*CDIM)

// ---------------- scratch (static device arrays; no runtime malloc) ----------------
__device__ __half g_xnh[RTOT*CDIM];      // layernormed x, fp16 (48 MB)
__device__ __half g_kvh[RTOT*KVC];       // exp(k)||v projections, fp16 (96 MB)
__device__ __half g_wrh[KVC*CDIM];       // fp16 Wkv
__device__ __half g_wqth[CC];            // fp16 Wq^T  [c][hd]
__device__ float  g_sumexp[BHN*DHEAD];   // softmax denominators
__device__ float  g_ctx[BHN*DHEAD*DHEAD];// sum exp(k)*v
__device__ __half g_uth[BATCH*CC];       // U^T_b [c3][hd], fp16
__device__ __half g_gth[BATCH*CC];       // Gt_b [c3][c], fp16 (incl. SCALE)
__device__ float  g_beff[BATCH*CDIM];    // folded bias per batch
__device__ float  g_zerob[CDIM];         // zero bias (never written -> stays 0)

__device__ __forceinline__ void cp16(void* s, const void* g) {
    unsigned sa = (unsigned)__cvta_generic_to_shared(s);
    asm volatile("cp.async.cg.shared.global [%0], [%1], 16;\n" :: "r"(sa), "l"(g));
}
__device__ __forceinline__ uint32_t smem_u32(const void* p) {
    uint32_t a;
    asm("{ .reg .u64 t; cvta.to.shared.u64 t, %1; cvt.u32.u64 %0, t; }"
        : "=r"(a) : "l"(p));
    return a;
}
#define LDM4(r0, r1, r2, r3, addr)                                              \
    asm volatile("ldmatrix.sync.aligned.m8n8.x4.shared.b16 {%0,%1,%2,%3}, [%4];"\
                 : "=r"(r0), "=r"(r1), "=r"(r2), "=r"(r3) : "r"(addr))
#define LDM4T(r0, r1, r2, r3, addr)                                             \
    asm volatile("ldmatrix.sync.aligned.m8n8.x4.trans.shared.b16 {%0,%1,%2,%3}, [%4];"\
                 : "=r"(r0), "=r"(r1), "=r"(r2), "=r"(r3) : "r"(addr))
#define MMA16816(c0, c1, c2, c3, a0, a1, a2, a3, b0, b1)                        \
    asm volatile(                                                               \
        "mma.sync.aligned.m16n8k16.row.col.f32.f16.f16.f32 "                   \
        "{%0,%1,%2,%3}, {%4,%5,%6,%7}, {%8,%9}, {%0,%1,%2,%3};\n"              \
        : "+f"(c0), "+f"(c1), "+f"(c2), "+f"(c3)                                \
        : "r"(a0), "r"(a1), "r"(a2), "r"(a3), "r"(b0), "r"(b1))

// ---------------- init accumulators ----------------
__global__ void init_k() {
    int i = blockIdx.x * blockDim.x + threadIdx.x;
    if (i < BHN*DHEAD) g_sumexp[i] = 0.f;
    if (i < BHN*DHEAD*DHEAD) g_ctx[i] = 0.f;
}

// ---------------- Wkv -> fp16 ; Wq -> fp16 transposed ----------------
__global__ void rnd_k(const float* __restrict__ w) {
    int i = blockIdx.x * blockDim.x + threadIdx.x;
    if (i < KVC*CDIM) g_wrh[i] = __float2half_rn(w[CC + i]);
    if (i < CC) {
        int hd = i / CDIM, c = i - hd * CDIM;
        g_wqth[c * CDIM + hd] = __float2half_rn(w[i]);
    }
}

// ---------------- LayerNorm: one block per row, fp16 output ----------------
__global__ __launch_bounds__(256) void ln_k(const float* __restrict__ x,
                                            const float* __restrict__ w,
                                            const float* __restrict__ b) {
    int row = blockIdx.x;
    int t = threadIdx.x;
    const float* xr = x + (long long)row * CDIM;
    float v0 = xr[t], v1 = xr[t + 256], v2 = xr[t + 512];
    float s  = v0 + v1 + v2;
    float ss = v0*v0 + v1*v1 + v2*v2;
    #pragma unroll
    for (int o = 16; o; o >>= 1) {
        s  += __shfl_xor_sync(0xffffffffu, s,  o);
        ss += __shfl_xor_sync(0xffffffffu, ss, o);
    }
    __shared__ float sh1[8], sh2[8];
    int wid = t >> 5, lid = t & 31;
    if (lid == 0) { sh1[wid] = s; sh2[wid] = ss; }
    __syncthreads();
    float ts = 0.f, tss = 0.f;
    #pragma unroll
    for (int i = 0; i < 8; i++) { ts += sh1[i]; tss += sh2[i]; }
    float mu   = ts * (1.f / CDIM);
    float var  = tss * (1.f / CDIM) - mu * mu;
    float rstd = rsqrtf(var + EPSLN);
    __half* o = g_xnh + (long long)row * CDIM;
    o[t]       = __float2half_rn((v0 - mu) * rstd * w[t]       + b[t]);
    o[t + 256] = __float2half_rn((v1 - mu) * rstd * w[t + 256] + b[t + 256]);
    o[t + 512] = __float2half_rn((v2 - mu) * rstd * w[t + 512] + b[t + 512]);
}

// ---------------- FP16 tensor-core GEMM (ldmatrix + mma.m16n8k16) ----------------
// A[m][k] row-major half (lda), B[n][k] row-major half (ldb),
// C[m][n] = alpha * sum_k A*B + bias[n]; columns n < expn get expf applied
// (fp32, post-bias) before output conversion. fp32 accum; OutT float or half.
#define H_STAGES 4
#define H_STAGE_BYTES 8192                 // 128 rows x 64 B
#define H_SMEM_BYTES (2 * H_STAGES * H_STAGE_BYTES)   // 65536

template <typename OutT>
__global__ __launch_bounds__(256, 2)
void gemm_h(const __half* __restrict__ A, const __half* __restrict__ B,
            const float* __restrict__ bias, OutT* __restrict__ C,
            int K, int lda, int ldb, int ldc, float alpha, int expn,
            long long bsA, long long bsB, long long bsC, int bsBias) {
    extern __shared__ __align__(1024) unsigned char hsm[];
    const uint32_t sbA = smem_u32(hsm);
    const uint32_t sbB = sbA + H_STAGES * H_STAGE_BYTES;

    const int t = threadIdx.x;
    const int lane = t & 31, wid = t >> 5;
    const int n0 = blockIdx.x * 128, m0 = blockIdx.y * 128;
    const __half* Ab = A + (long long)blockIdx.z * bsA;
    const __half* Bb = B + (long long)blockIdx.z * bsB;
    OutT*         Cb = C + (long long)blockIdx.z * bsC;
    const float* biasb = bias + (long long)blockIdx.z * bsBias;

    const int wm = (wid >> 2) * 64, wn = (wid & 3) * 32;
    const int grp = lane >> 2, thr = lane & 3;
    const int lr = t >> 1, lcp = (t & 1) << 1;

    float acc[4][4][4];
    #pragma unroll
    for (int i = 0; i < 4; i++)
        #pragma unroll
        for (int j = 0; j < 4; j++)
            #pragma unroll
            for (int q = 0; q < 4; q++) acc[i][j][q] = 0.f;

    #define H_LOAD(slot, k0)                                                    \
        do {                                                                    \
            _Pragma("unroll")                                                   \
            for (int c2 = 0; c2 < 2; c2++) {                                    \
                int ch = lcp + c2;                                              \
                int sw = lr * 64 + ((ch ^ ((lr >> 1) & 3)) << 4);               \
                cp16(hsm + (slot) * H_STAGE_BYTES + sw,                         \
                     Ab + (long long)(m0 + lr) * lda + (k0) + ch * 8);          \
                cp16(hsm + (H_STAGES + (slot)) * H_STAGE_BYTES + sw,            \
                     Bb + (long long)(n0 + lr) * ldb + (k0) + ch * 8);          \
            }                                                                   \
            asm volatile("cp.async.commit_group;\n");                           \
        } while (0)

    const int T = K >> 5;   // K / 32
    H_LOAD(0, 0);
    H_LOAD(1, 32);
    H_LOAD(2, 64);

    const int arow = (lane & 15);
    const int brow = (lane & 7) + ((lane >> 4) << 3);
    const int acs  = lane >> 4;
    const int bcs  = (lane >> 3) & 1;

    for (int tt = 0; tt < T; tt++) {
        asm volatile("cp.async.wait_group 2;\n" ::: "memory");
        __syncthreads();
        if (tt + 3 < T) {
            H_LOAD((tt + 3) & (H_STAGES - 1), (tt + 3) << 5);
        } else {
            asm volatile("cp.async.commit_group;\n");
        }
        const int slot = tt & (H_STAGES - 1);
        const uint32_t aBase = sbA + slot * H_STAGE_BYTES;
        const uint32_t bBase = sbB + slot * H_STAGE_BYTES;
        #pragma unroll
        for (int kk = 0; kk < 32; kk += 16) {
            uint32_t a[4][4], b[2][4];
            #pragma unroll
            for (int mi = 0; mi < 4; mi++) {
                int row = wm + mi * 16 + arow;
                int ch = (kk >> 3) + acs;
                uint32_t ad = aBase + row * 64 + ((ch ^ ((row >> 1) & 3)) << 4);
                LDM4(a[mi][0], a[mi][1], a[mi][2], a[mi][3], ad);
            }
            #pragma unroll
            for (int njp = 0; njp < 2; njp++) {
                int row = wn + njp * 16 + brow;
                int ch = (kk >> 3) + bcs;
                uint32_t bd = bBase + row * 64 + ((ch ^ ((row >> 1) & 3)) << 4);
                LDM4(b[njp][0], b[njp][1], b[njp][2], b[njp][3], bd);
            }
            #pragma unroll
            for (int mi = 0; mi < 4; mi++)
                #pragma unroll
                for (int nj = 0; nj < 4; nj++)
                    MMA16816(acc[mi][nj][0], acc[mi][nj][1],
                             acc[mi][nj][2], acc[mi][nj][3],
                             a[mi][0], a[mi][1], a[mi][2], a[mi][3],
                             b[nj >> 1][(nj & 1) * 2],
                             b[nj >> 1][(nj & 1) * 2 + 1]);
        }
    }
    #undef H_LOAD

    const bool doexp = (n0 < expn);
    #pragma unroll
    for (int mi = 0; mi < 4; mi++) {
        #pragma unroll
        for (int nj = 0; nj < 4; nj++) {
            int m = m0 + wm + mi * 16 + grp;
            int n = n0 + wn + nj * 8 + 2 * thr;
            float bi0 = biasb[n], bi1 = biasb[n + 1];
            float o00 = alpha * acc[mi][nj][0] + bi0;
            float o01 = alpha * acc[mi][nj][1] + bi1;
            float o10 = alpha * acc[mi][nj][2] + bi0;
            float o11 = alpha * acc[mi][nj][3] + bi1;
            if (doexp) {
                o00 = __expf(o00); o01 = __expf(o01);
                o10 = __expf(o10); o11 = __expf(o11);
            }
            if constexpr (sizeof(OutT) == 4) {
                *(float2*)&Cb[(long long)m * ldc + n] = make_float2(o00, o01);
                *(float2*)&Cb[(long long)(m + 8) * ldc + n] = make_float2(o10, o11);
            } else {
                *(__half2*)&Cb[(long long)m * ldc + n] = __floats2half2_rn(o00, o01);
                *(__half2*)&Cb[(long long)(m + 8) * ldc + n] = __floats2half2_rn(o10, o11);
            }
        }
    }
}

// ---------------- ctx via tensor cores ----------------
// ctx[bh][d][e] += sum_n ek[n,d] * v[n,e];  sumexp[bh][d] += sum_n ek[n,d]
// ek/v stored seq-major in g_kvh; logical feat-major operands obtained with
// ldmatrix.x4.trans. sumexp via one extra MMA with constant all-ones B.
#define CTX_ROWS 128
__global__ __launch_bounds__(128) void ctxm_k() {
    __shared__ __align__(1024) __half ks[CTX_ROWS * 64];
    __shared__ __align__(1024) __half vs[CTX_ROWS * 64];
    int bh = blockIdx.x, ch = blockIdx.y;
    int b = bh / HEADS, h = bh - b * HEADS;
    int t = threadIdx.x, lane = t & 31, w = t >> 5;

    long long gbase = ((long long)(b * NSEQ + ch * CTX_ROWS)) * KVC + h * 64;
    #pragma unroll
    for (int i = 0; i < 8; i++) {
        int idx = t + i * 128;
        int row = idx >> 3, c = idx & 7;
        int cw = c ^ (row & 7);
        cp16((char*)ks + row * 128 + cw * 16,
             g_kvh + gbase + (long long)row * KVC + c * 8);
        cp16((char*)vs + row * 128 + cw * 16,
             g_kvh + gbase + (long long)row * KVC + 768 + c * 8);
    }
    asm volatile("cp.async.commit_group;\n");
    asm volatile("cp.async.wait_group 0;\n" ::: "memory");
    __syncthreads();

    uint32_t ksb = smem_u32(ks), vsb = smem_u32(vs);
    const int m0 = w * 16;                       // d-slice per warp
    float acc[8][4];
    float so[4] = {0.f, 0.f, 0.f, 0.f};
    #pragma unroll
    for (int i = 0; i < 8; i++)
        #pragma unroll
        for (int q = 0; q < 4; q++) acc[i][q] = 0.f;

    // A (ek^T, m=d k=n): lanes 0-7:(k0-7,m0) 8-15:(k0-7,m0+8) 16-23:(k8-15,m0) 24-31:(k8-15,m0+8)
    const int rA = (lane & 7) + ((lane >> 4) << 3);
    const int cA = (m0 >> 3) + ((lane >> 3) & 1);
    // B (v^T, n=e k=n): lanes 0-7:(k0-7,n0) 8-15:(k8-15,n0) 16-23:(k0-7,n0+8) 24-31:(k8-15,n0+8)
    const int rB = (lane & 7) + (((lane >> 3) & 1) << 3);
    const uint32_t ones2 = 0x3C003C00u;          // (1.0h, 1.0h)

    #pragma unroll
    for (int s = 0; s < CTX_ROWS / 16; s++) {
        int k0 = s * 16;
        uint32_t a0, a1, a2, a3;
        {
            int r = k0 + rA;
            LDM4T(a0, a1, a2, a3, ksb + r * 128 + ((cA ^ (r & 7)) << 4));
        }
        uint32_t bf[4][4];
        #pragma unroll
        for (int njp = 0; njp < 4; njp++) {
            int r = k0 + rB;
            int c = njp * 2 + (lane >> 4);
            LDM4T(bf[njp][0], bf[njp][1], bf[njp][2], bf[njp][3],
                  vsb + r * 128 + ((c ^ (r & 7)) << 4));
        }
        #pragma unroll
        for (int nj = 0; nj < 8; nj++)
            MMA16816(acc[nj][0], acc[nj][1], acc[nj][2], acc[nj][3],
                     a0, a1, a2, a3,
                     bf[nj >> 1][(nj & 1) * 2], bf[nj >> 1][(nj & 1) * 2 + 1]);
        MMA16816(so[0], so[1], so[2], so[3], a0, a1, a2, a3, ones2, ones2);
    }

    int grp = lane >> 2, thr = lane & 3;
    float* cb = &g_ctx[bh * 4096];
    #pragma unroll
    for (int nj = 0; nj < 8; nj++) {
        int e = nj * 8 + 2 * thr;
        atomicAdd(&cb[(m0 + grp) * 64 + e],     acc[nj][0]);
        atomicAdd(&cb[(m0 + grp) * 64 + e + 1], acc[nj][1]);
        atomicAdd(&cb[(m0 + grp + 8) * 64 + e],     acc[nj][2]);
        atomicAdd(&cb[(m0 + grp + 8) * 64 + e + 1], acc[nj][3]);
    }
    if (thr == 0) {
        atomicAdd(&g_sumexp[bh * 64 + m0 + grp],     so[0]);
        atomicAdd(&g_sumexp[bh * 64 + m0 + grp + 8], so[2]);
    }
}

// ---------------- U^T_b[c3][h*64+d] = sum_e (ctx[d,e]/sumexp[d]) * proj_w[c3, h*64+e] ----------------
__global__ __launch_bounds__(256) void u_k(const float* __restrict__ pw) {
    int bh = blockIdx.x;
    int c30 = blockIdx.y * 64;
    int b = bh / HEADS, h = bh - b * HEADS;
    int t = threadIdx.x;
    __shared__ float inv[64];
    __shared__ float sce[64][68];  // [e][d]
    __shared__ float spw[64][68];  // [e][c3_local]
    if (t < 64) inv[t] = 1.f / g_sumexp[bh * 64 + t];
    __syncthreads();
    #pragma unroll
    for (int i = 0; i < 16; i++) {
        int idx = t + i * 256;
        int d = idx >> 6, e = idx & 63;
        sce[e][d] = g_ctx[bh * 4096 + idx] * inv[d];
    }
    #pragma unroll
    for (int i = 0; i < 16; i++) {
        int idx = t + i * 256;
        int c3l = idx >> 6, e = idx & 63;
        spw[e][c3l] = pw[(long long)(c30 + c3l) * CDIM + h * 64 + e];
    }
    __syncthreads();
    int d0 = (t & 15) * 4, c0 = (t >> 4) * 4;
    float acc[4][4];
    #pragma unroll
    for (int i = 0; i < 4; i++)
        #pragma unroll
        for (int j = 0; j < 4; j++) acc[i][j] = 0.f;
    #pragma unroll 8
    for (int e = 0; e < 64; e++) {
        float4 a  = *(float4*)&sce[e][d0];
        float4 bb = *(float4*)&spw[e][c0];
        float av[4] = {a.x, a.y, a.z, a.w};
        float bv[4] = {bb.x, bb.y, bb.z, bb.w};
        #pragma unroll
        for (int i = 0; i < 4; i++)
            #pragma unroll
            for (int j = 0; j < 4; j++) acc[i][j] += av[i] * bv[j];
    }
    __half* Ut = &g_uth[(long long)b * CC];
    #pragma unroll
    for (int i = 0; i < 4; i++)
        #pragma unroll
        for (int j = 0; j < 4; j++)
            Ut[(long long)(c30 + c0 + j) * CDIM + h * 64 + d0 + i] =
                __float2half_rn(acc[i][j]);
}

// ---------------- b_eff[b][c3] = scale * sum_hd qkv_b[hd]*U^T[c3][hd] + proj_b[c3] ----------------
__global__ __launch_bounds__(256) void beff_k(const float* __restrict__ qb,
                                              const float* __restrict__ pb) {
    int b = blockIdx.x;
    int c3 = blockIdx.y * 256 + threadIdx.x;
    const __half* Ut = &g_uth[(long long)b * CC + (long long)c3 * CDIM];
    float acc = pb[c3];
    #pragma unroll 8
    for (int hd = 0; hd < CDIM; hd++)
        acc += SCALE * qb[hd] * __half2float(Ut[hd]);
    g_beff[b * CDIM + c3] = acc;
}

// ---------------- launch ----------------
extern "C" void kernel_launch(void* const* d_in, const int* in_sizes, int n_in,
                              void* d_out, int out_size) {
    const float* x      = (const float*)d_in[0];
    const float* ln_w   = (const float*)d_in[1];
    const float* ln_b   = (const float*)d_in[2];
    const float* qkv_w  = (const float*)d_in[3];
    const float* qkv_b  = (const float*)d_in[4];
    const float* proj_w = (const float*)d_in[5];
    const float* proj_b = (const float*)d_in[6];
    float* out = (float*)d_out;

    static __half* xnh_p = nullptr;
    static __half* kvh_p = nullptr;
    static __half* wrh_p = nullptr;
    static __half* wqth_p = nullptr;
    static __half* uth_p = nullptr;
    static __half* gth_p = nullptr;
    static float*  beff_p = nullptr;
    static float*  zerob_p = nullptr;
    if (!xnh_p) {
        cudaGetSymbolAddress((void**)&xnh_p, g_xnh);
        cudaGetSymbolAddress((void**)&kvh_p, g_kvh);
        cudaGetSymbolAddress((void**)&wrh_p, g_wrh);
        cudaGetSymbolAddress((void**)&wqth_p, g_wqth);
        cudaGetSymbolAddress((void**)&uth_p, g_uth);
        cudaGetSymbolAddress((void**)&gth_p, g_gth);
        cudaGetSymbolAddress((void**)&beff_p, g_beff);
        cudaGetSymbolAddress((void**)&zerob_p, g_zerob);
        cudaFuncSetAttribute(gemm_h<__half>,
                             cudaFuncAttributeMaxDynamicSharedMemorySize,
                             H_SMEM_BYTES);
        cudaFuncSetAttribute(gemm_h<float>,
                             cudaFuncAttributeMaxDynamicSharedMemorySize,
                             H_SMEM_BYTES);
    }

    // 1. reset accumulators
    init_k<<<768, 256>>>();
    // 2. weights -> fp16 (Wkv rows, Wq transposed)
    rnd_k<<<(KVC * CDIM + 255) / 256, 256>>>(qkv_w);
    // 3. LayerNorm (fp16 output)
    ln_k<<<RTOT, 256>>>(x, ln_w, ln_b);
    // 4. ek||v = exp/id(xn @ Wkv^T + bkv)  (fp16 tensor cores; exp on cols<768)
    gemm_h<__half><<<dim3(KVC / 128, RTOT / 128, 1), 256, H_SMEM_BYTES>>>(
        xnh_p, wrh_p, qkv_b + CDIM, kvh_p,
        CDIM, CDIM, CDIM, KVC, 1.f, CDIM, 0, 0, 0, 0);
    // 5. ctx + sumexp via tensor cores
    ctxm_k<<<dim3(BHN, NSEQ / CTX_ROWS), 128>>>();
    // 6. U^T_b (fp16) = blockdiag(ctx_norm) applied to proj_w
    u_k<<<dim3(BHN, CDIM / 64), 256>>>(proj_w);
    // 7. effective bias
    beff_k<<<dim3(BATCH, CDIM / 256), 256>>>(qkv_b, proj_b);
    // 8. Gt_b[c3][c] = SCALE * U^T_b @ Wq  (fp16 tensor cores)
    gemm_h<__half><<<dim3(CDIM / 128, CDIM / 128, BATCH), 256, H_SMEM_BYTES>>>(
        uth_p, wqth_p, zerob_p, gth_p,
        CDIM, CDIM, CDIM, CDIM, SCALE, 0,
        (long long)CC, 0, (long long)CC, 0);
    // 9. final = xn[b] @ Gt_b^T + b_eff[b]   (fp16 tensor cores, fp32 output)
    gemm_h<float><<<dim3(CDIM / 128, NSEQ / 128, BATCH), 256, H_SMEM_BYTES>>>(
        xnh_p, gth_p, beff_p, out,
        CDIM, CDIM, CDIM, CDIM, 1.f, 0,
        (long long)NSEQ * CDIM, (long long)CC,
        (long long)NSEQ * CDIM, CDIM);
}